// round 1
// baseline (speedup 1.0000x reference)
#include <cuda_runtime.h>
#include <cuda_bf16.h>
#include <math.h>

// ---------------- problem dims ----------------
#define HID     2048
#define HEADS   16
#define SEQ     2048
#define BATCH   2
#define BS      (BATCH*SEQ)          // 4096
#define QLORA   1024
#define QH      192                  // NOPE + ROPE
#define NOPE    128
#define ROPED   64
#define VH      128
#define KVL     512
#define CKV_W   576                  // KVL + ROPED
#define QW      (HEADS*QH)           // 3072
#define KVW     (HEADS*(NOPE+VH))    // 4096

// ---------------- scratch (static device globals; no allocation) ----------------
__device__ float g_cq  [(size_t)BS * QLORA];   // 16 MB
__device__ float g_q   [(size_t)BS * QW];      // 48 MB
__device__ float g_ckv [(size_t)BS * CKV_W];   //  9 MB
__device__ float g_kv  [(size_t)BS * KVW];     // 64 MB
__device__ float g_attn[(size_t)BS * HID];     // 32 MB

// =====================================================================
// Generic row-major SGEMM: C[M,N] = A[M,K] @ B[K,N]
// 128x128 tile, BK=16, 256 threads, 8x8 microtile.
// Requires M%128==0, K%16==0, lda/ldb/ldc %4==0. N guarded.
// =====================================================================
__global__ __launch_bounds__(256)
void sgemm128(const float* __restrict__ A, const float* __restrict__ B,
              float* __restrict__ C,
              int M, int N, int K, int lda, int ldb, int ldc)
{
    __shared__ float As[16][132];   // transposed A tile, padded
    __shared__ float Bs[16][128];

    const int tid = threadIdx.x;
    const int tx = tid & 15, ty = tid >> 4;
    const int m0 = blockIdx.y * 128;
    const int n0 = blockIdx.x * 128;

    float acc[8][8];
    #pragma unroll
    for (int i = 0; i < 8; i++)
        #pragma unroll
        for (int j = 0; j < 8; j++) acc[i][j] = 0.f;

    for (int k0 = 0; k0 < K; k0 += 16) {
        // load A tile: 128 rows x 16 cols (512 float4)
        #pragma unroll
        for (int t = 0; t < 2; t++) {
            int idx = tid + t * 256;
            int r = idx >> 2, c4 = idx & 3;
            float4 v = *(const float4*)(A + (size_t)(m0 + r) * lda + k0 + c4 * 4);
            As[c4*4 + 0][r] = v.x;
            As[c4*4 + 1][r] = v.y;
            As[c4*4 + 2][r] = v.z;
            As[c4*4 + 3][r] = v.w;
        }
        // load B tile: 16 rows x 128 cols (512 float4), N-guarded
        #pragma unroll
        for (int t = 0; t < 2; t++) {
            int idx = tid + t * 256;
            int r = idx >> 5, c4 = idx & 31;
            int gcol = n0 + c4 * 4;
            float4 v = make_float4(0.f, 0.f, 0.f, 0.f);
            if (gcol < N)
                v = *(const float4*)(B + (size_t)(k0 + r) * ldb + gcol);
            *(float4*)&Bs[r][c4 * 4] = v;
        }
        __syncthreads();

        #pragma unroll
        for (int kk = 0; kk < 16; kk++) {
            float a[8], b[8];
            *(float4*)&a[0] = *(const float4*)&As[kk][ty * 8];
            *(float4*)&a[4] = *(const float4*)&As[kk][ty * 8 + 4];
            *(float4*)&b[0] = *(const float4*)&Bs[kk][tx * 8];
            *(float4*)&b[4] = *(const float4*)&Bs[kk][tx * 8 + 4];
            #pragma unroll
            for (int i = 0; i < 8; i++)
                #pragma unroll
                for (int j = 0; j < 8; j++)
                    acc[i][j] += a[i] * b[j];
        }
        __syncthreads();
    }

    #pragma unroll
    for (int i = 0; i < 8; i++) {
        size_t row = (size_t)(m0 + ty * 8 + i);
        #pragma unroll
        for (int jj = 0; jj < 2; jj++) {
            int col = n0 + tx * 8 + jj * 4;
            if (col < N) {
                float4 v = make_float4(acc[i][jj*4+0], acc[i][jj*4+1],
                                       acc[i][jj*4+2], acc[i][jj*4+3]);
                *(float4*)(C + row * ldc + col) = v;
            }
        }
    }
}

// =====================================================================
// RoPE: q rope halves (per head) and k_rope in ckv (shared across heads)
// idx -> (bs, h in 0..16, j in 0..31); h==16 means ckv path.
// =====================================================================
__global__ void rope_kernel(float* __restrict__ q, float* __restrict__ ckv,
                            const int* __restrict__ position)
{
    int idx = blockIdx.x * blockDim.x + threadIdx.x;
    const int total = BS * 17 * 32;
    if (idx >= total) return;
    int j = idx & 31;
    int rest = idx >> 5;
    int h = rest % 17;
    int bs = rest / 17;
    int s = bs & (SEQ - 1);

    float pos = (float)position[s];
    // inv_freq = 10000^(-2j/64) = exp(-(2j/64)*ln(10000))
    float inv = __expf(-(float)(2 * j) * (9.210340371976184f / 64.0f));
    float ang = pos * inv;
    float sn, cs;
    sincosf(ang, &sn, &cs);

    float* base = (h < 16)
        ? (q + (size_t)bs * QW + h * QH + NOPE)
        : (ckv + (size_t)bs * CKV_W + KVL);
    float t1 = base[j];
    float t2 = base[j + 32];
    base[j]      = t1 * cs - t2 * sn;
    base[j + 32] = t2 * cs + t1 * sn;
}

// =====================================================================
// Flash attention (non-causal), fp32.
// Block: (q_tile=64 rows, head, batch). 256 threads.
// BK = 32 keys/iter. Thread (tx,ty): rows ty*4..+4 ; score cols {tx, tx+16};
// out f4-cols {tx, tx+16}.
// smem (floats): Qs[64][196] Ks[32][196] Vs[32][128] Ps[64][33]
// =====================================================================
#define ATTN_SMEM_FLOATS (64*196 + 32*196 + 32*128 + 64*33)
#define ATTN_SMEM_BYTES  (ATTN_SMEM_FLOATS * 4)

__global__ __launch_bounds__(256)
void attn_kernel(const float* __restrict__ q, const float* __restrict__ kv,
                 const float* __restrict__ ckv, float* __restrict__ out)
{
    extern __shared__ float sm[];
    float* Qs = sm;                       // [64][196]
    float* Ks = Qs + 64 * 196;            // [32][196]
    float* Vs = Ks + 32 * 196;            // [32][128]
    float* Ps = Vs + 32 * 128;            // [64][33]

    const int b  = blockIdx.z;
    const int h  = blockIdx.y;
    const int q0 = blockIdx.x * 64;
    const int tid = threadIdx.x;
    const int tx = tid & 15, ty = tid >> 4;

    // load Q tile once: 64 x 192 (48 float4 per row)
    const float* qbase = q + (size_t)(b * SEQ + q0) * QW + h * QH;
    for (int i = tid; i < 64 * 48; i += 256) {
        int r = i / 48, c4 = i % 48;
        ((float4*)(Qs + r * 196))[c4] = ((const float4*)(qbase + (size_t)r * QW))[c4];
    }

    float mrow[4], lrow[4], acc[4][8];
    #pragma unroll
    for (int i = 0; i < 4; i++) {
        mrow[i] = -1e30f; lrow[i] = 0.f;
        #pragma unroll
        for (int j = 0; j < 8; j++) acc[i][j] = 0.f;
    }
    const float scale = 0.07216878364870323f;  // 1/sqrt(192)

    for (int kt = 0; kt < SEQ / 32; kt++) {
        __syncthreads();  // prev iter done with Ks/Vs/Ps
        // load K tile 32x192: cols<128 from kv (nope), cols>=128 from ckv (rope)
        for (int i = tid; i < 32 * 48; i += 256) {
            int r = i / 48, c4 = i % 48;
            size_t row = (size_t)(b * SEQ + kt * 32 + r);
            float4 v;
            if (c4 < 32) v = ((const float4*)(kv + row * KVW + h * 256))[c4];
            else         v = ((const float4*)(ckv + row * CKV_W + KVL))[c4 - 32];
            ((float4*)(Ks + r * 196))[c4] = v;
        }
        // load V tile 32x128
        for (int i = tid; i < 32 * 32; i += 256) {
            int r = i >> 5, c4 = i & 31;
            ((float4*)(Vs + r * 128))[c4] =
                ((const float4*)(kv + (size_t)(b * SEQ + kt * 32 + r) * KVW + h * 256 + NOPE))[c4];
        }
        __syncthreads();

        // scores: S[4 rows][2 cols]
        float s0[4] = {0.f, 0.f, 0.f, 0.f};
        float s1[4] = {0.f, 0.f, 0.f, 0.f};
        const float4* kb0 = (const float4*)(Ks + tx * 196);
        const float4* kb1 = (const float4*)(Ks + (tx + 16) * 196);
        #pragma unroll 4
        for (int d4 = 0; d4 < 48; d4++) {
            float4 ka = kb0[d4];
            float4 kc = kb1[d4];
            #pragma unroll
            for (int i = 0; i < 4; i++) {
                float4 qv = ((const float4*)(Qs + (ty * 4 + i) * 196))[d4];
                s0[i] += qv.x * ka.x + qv.y * ka.y + qv.z * ka.z + qv.w * ka.w;
                s1[i] += qv.x * kc.x + qv.y * kc.y + qv.z * kc.z + qv.w * kc.w;
            }
        }

        // online softmax update
        #pragma unroll
        for (int i = 0; i < 4; i++) {
            float a = s0[i] * scale;
            float c = s1[i] * scale;
            float rm = fmaxf(a, c);
            #pragma unroll
            for (int off = 8; off; off >>= 1)
                rm = fmaxf(rm, __shfl_xor_sync(0xffffffffu, rm, off));
            float mnew  = fmaxf(mrow[i], rm);
            float alpha = __expf(mrow[i] - mnew);
            float p0 = __expf(a - mnew);
            float p1 = __expf(c - mnew);
            float rs = p0 + p1;
            #pragma unroll
            for (int off = 8; off; off >>= 1)
                rs += __shfl_xor_sync(0xffffffffu, rs, off);
            lrow[i] = lrow[i] * alpha + rs;
            mrow[i] = mnew;
            #pragma unroll
            for (int j = 0; j < 8; j++) acc[i][j] *= alpha;
            Ps[(ty * 4 + i) * 33 + tx]      = p0;
            Ps[(ty * 4 + i) * 33 + tx + 16] = p1;
        }
        __syncthreads();

        // PV: acc += P[64x32] @ V[32x128]
        #pragma unroll 4
        for (int k = 0; k < 32; k++) {
            float4 v0 = ((const float4*)(Vs + k * 128))[tx];
            float4 v1 = ((const float4*)(Vs + k * 128))[tx + 16];
            #pragma unroll
            for (int i = 0; i < 4; i++) {
                float p = Ps[(ty * 4 + i) * 33 + k];
                acc[i][0] += p * v0.x; acc[i][1] += p * v0.y;
                acc[i][2] += p * v0.z; acc[i][3] += p * v0.w;
                acc[i][4] += p * v1.x; acc[i][5] += p * v1.y;
                acc[i][6] += p * v1.z; acc[i][7] += p * v1.w;
            }
        }
    }

    // normalize + store: out[(b*SEQ + row)][h*128 + col]
    #pragma unroll
    for (int i = 0; i < 4; i++) {
        float inv = 1.0f / lrow[i];
        float4 o0 = make_float4(acc[i][0]*inv, acc[i][1]*inv, acc[i][2]*inv, acc[i][3]*inv);
        float4 o1 = make_float4(acc[i][4]*inv, acc[i][5]*inv, acc[i][6]*inv, acc[i][7]*inv);
        float* ob = out + (size_t)(b * SEQ + q0 + ty * 4 + i) * HID + h * VH;
        ((float4*)ob)[tx]      = o0;
        ((float4*)ob)[tx + 16] = o1;
    }
}

// =====================================================================
extern "C" void kernel_launch(void* const* d_in, const int* in_sizes, int n_in,
                              void* d_out, int out_size)
{
    const float* x        = (const float*)d_in[0];
    const int*   position = (const int*)  d_in[1];
    const float* Wq_down  = (const float*)d_in[2];
    const float* Wq_up    = (const float*)d_in[3];
    const float* Wkv_down = (const float*)d_in[4];
    const float* Wkv_up   = (const float*)d_in[5];
    const float* Wout     = (const float*)d_in[6];
    float*       out      = (float*)d_out;

    float *cq, *qb, *ckv, *kvb, *attn;
    cudaGetSymbolAddress((void**)&cq,   g_cq);
    cudaGetSymbolAddress((void**)&qb,   g_q);
    cudaGetSymbolAddress((void**)&ckv,  g_ckv);
    cudaGetSymbolAddress((void**)&kvb,  g_kv);
    cudaGetSymbolAddress((void**)&attn, g_attn);

    cudaFuncSetAttribute(attn_kernel, cudaFuncAttributeMaxDynamicSharedMemorySize,
                         ATTN_SMEM_BYTES);

    dim3 blk(256);

    // cq = x @ Wq_down                    (4096,1024,2048)
    sgemm128<<<dim3(QLORA/128, BS/128), blk>>>(x, Wq_down, cq,
                                               BS, QLORA, HID, HID, QLORA, QLORA);
    // q = cq @ Wq_up                      (4096,3072,1024)
    sgemm128<<<dim3(QW/128, BS/128), blk>>>(cq, Wq_up, qb,
                                            BS, QW, QLORA, QLORA, QW, QW);
    // ckv = x @ Wkv_down                  (4096,576,2048) — N guarded
    sgemm128<<<dim3((CKV_W + 127)/128, BS/128), blk>>>(x, Wkv_down, ckv,
                                                       BS, CKV_W, HID, HID, CKV_W, CKV_W);
    // RoPE on q rope halves and ckv[:,512:576]
    rope_kernel<<<(BS*17*32 + 255)/256, 256>>>(qb, ckv, position);
    // kv = ckv[:, :512] @ Wkv_up          (4096,4096,512)
    sgemm128<<<dim3(KVW/128, BS/128), blk>>>(ckv, Wkv_up, kvb,
                                             BS, KVW, KVL, CKV_W, KVW, KVW);
    // attention
    attn_kernel<<<dim3(SEQ/64, HEADS, BATCH), 256, ATTN_SMEM_BYTES>>>(qb, kvb, ckv, attn);
    // out = attn @ Wout                   (4096,2048,2048)
    sgemm128<<<dim3(HID/128, BS/128), blk>>>(attn, Wout, out,
                                             BS, HID, HID, HID, HID, HID);
}

// round 3
// speedup vs baseline: 1.3160x; 1.3160x over previous
#include <cuda_runtime.h>
#include <cuda_bf16.h>
#include <math.h>
#include <stdint.h>

// ---------------- problem dims ----------------
#define HID     2048
#define HEADS   16
#define SEQ     2048
#define BATCH   2
#define BS      (BATCH*SEQ)          // 4096
#define QLORA   1024
#define QH      192
#define NOPE    128
#define ROPED   64
#define VH      128
#define KVL     512
#define CKV_W   576
#define QW      (HEADS*QH)           // 3072
#define KVW     (HEADS*(NOPE+VH))    // 4096

// ---------------- scratch ----------------
__device__ float g_cq  [(size_t)BS * QLORA];
__device__ float g_q   [(size_t)BS * QW];
__device__ float g_ckv [(size_t)BS * CKV_W];
__device__ float g_kv  [(size_t)BS * KVW];
__device__ float g_attn[(size_t)BS * HID];
// transposed + hi/lo split bf16 weights
#define WQD_SZ  (1024*2048)
#define WQU_SZ  (3072*1024)
#define WKD_SZ  (576*2048)
#define WKU_SZ  (4096*512)
#define WO_SZ   (2048*2048)
#define O_WQD_HI 0
#define O_WQD_LO (O_WQD_HI + WQD_SZ)
#define O_WQU_HI (O_WQD_LO + WQD_SZ)
#define O_WQU_LO (O_WQU_HI + WQU_SZ)
#define O_WKD_HI (O_WQU_LO + WQU_SZ)
#define O_WKD_LO (O_WKD_HI + WKD_SZ)
#define O_WKU_HI (O_WKD_LO + WKD_SZ)
#define O_WKU_LO (O_WKU_HI + WKU_SZ)
#define O_WO_HI  (O_WKU_LO + WKU_SZ)
#define O_WO_LO  (O_WO_HI + WO_SZ)
#define W_TOTAL  (O_WO_LO + WO_SZ)
__device__ __nv_bfloat16 g_w[W_TOTAL];

// ---------------- helpers ----------------
__device__ __forceinline__ uint32_t smem_u32(const void* p) {
    uint32_t a;
    asm("{ .reg .u64 t; cvta.to.shared.u64 t, %1; cvt.u32.u64 %0, t; }"
        : "=r"(a) : "l"(p));
    return a;
}
// SW64 swizzle for 64-byte rows: bits[5:4] ^= bits[8:7]
#define SWZ64(o) ((o) ^ (((o) >> 3) & 0x30))

__device__ __forceinline__ void ldm_x4(uint32_t addr, uint32_t r[4]) {
    asm volatile("ldmatrix.sync.aligned.m8n8.x4.shared.b16 {%0,%1,%2,%3}, [%4];"
                 : "=r"(r[0]), "=r"(r[1]), "=r"(r[2]), "=r"(r[3]) : "r"(addr));
}
__device__ __forceinline__ void mma16816(float d[4], const uint32_t a[4],
                                         const uint32_t b0, const uint32_t b1) {
    asm volatile("mma.sync.aligned.m16n8k16.row.col.f32.bf16.bf16.f32 "
                 "{%0,%1,%2,%3}, {%4,%5,%6,%7}, {%8,%9}, {%0,%1,%2,%3};"
                 : "+f"(d[0]), "+f"(d[1]), "+f"(d[2]), "+f"(d[3])
                 : "r"(a[0]), "r"(a[1]), "r"(a[2]), "r"(a[3]), "r"(b0), "r"(b1));
}

// =====================================================================
// Weight transpose + hi/lo bf16 split: W[K,N] -> Whi/Wlo[N,K]
// =====================================================================
__global__ __launch_bounds__(256)
void wconv(const float* __restrict__ W, __nv_bfloat16* __restrict__ hi,
           __nv_bfloat16* __restrict__ lo, int K, int N)
{
    __shared__ float t[32][33];
    int n0 = blockIdx.x * 32, k0 = blockIdx.y * 32;
    int tx = threadIdx.x & 31, ty = threadIdx.x >> 5;
    #pragma unroll
    for (int j = 0; j < 4; j++)
        t[ty + 8*j][tx] = W[(size_t)(k0 + ty + 8*j) * N + n0 + tx];
    __syncthreads();
    #pragma unroll
    for (int j = 0; j < 4; j++) {
        float v = t[tx][ty + 8*j];
        __nv_bfloat16 h = __float2bfloat16(v);
        __nv_bfloat16 l = __float2bfloat16(v - __bfloat162float(h));
        size_t o = (size_t)(n0 + ty + 8*j) * K + k0 + tx;
        hi[o] = h;
        lo[o] = l;
    }
}

// =====================================================================
// mma.sync bf16 hi/lo-split GEMM: C[M,N] = A[M,K] @ B[K,N]
// A fp32 row-major; B pre-transposed hi/lo bf16 [N,K].
// CTA tile 128x128, BK=32, 8 warps (2x4), warp tile 64x32.
// Double-buffered smem, reg-staged global loads.
// smem per buffer: Ah 8K | Al 8K | Bh 8K | Bl 8K = 32KB; x2 = 64KB
// =====================================================================
#define GEMM_SMEM 65536

__global__ __launch_bounds__(256, 1)
void gemm_mma(const float* __restrict__ A,
              const __nv_bfloat16* __restrict__ Bhi,
              const __nv_bfloat16* __restrict__ Blo,
              float* __restrict__ C,
              int M, int N, int K, int lda, int ldc)
{
    extern __shared__ char sm[];
    const uint32_t sb = smem_u32(sm);
    const int tid  = threadIdx.x;
    const int lane = tid & 31;
    const int wid  = tid >> 5;
    const int wm   = (wid >> 2) * 64;   // warp m offset (0 or 64)
    const int wn   = (wid & 3) * 32;    // warp n offset
    const int m0   = blockIdx.y * 128;
    const int n0   = blockIdx.x * 128;

    float acc[4][4][4];
    #pragma unroll
    for (int i = 0; i < 4; i++)
        #pragma unroll
        for (int j = 0; j < 4; j++)
            #pragma unroll
            for (int c = 0; c < 4; c++) acc[i][j][c] = 0.f;

    // staging regs
    float4 sa[4];
    uint4  sbh[2], sbl[2];

    const int T = K >> 5;

    // thread's load coordinates
    const int ar = tid >> 3, ac4 = tid & 7;        // A: +256 -> +32 rows
    const int br = tid >> 2, bc4 = tid & 3;        // B: +256 -> +64 rows

    // ---- load tile t into regs ----
    auto G = [&](int t) {
        const int k0 = t << 5;
        #pragma unroll
        for (int i = 0; i < 4; i++)
            sa[i] = *(const float4*)(A + (size_t)(m0 + ar + i * 32) * lda + k0 + ac4 * 4);
        #pragma unroll
        for (int i = 0; i < 2; i++) {
            int n = n0 + br + i * 64;
            if (n < N) {
                sbh[i] = ((const uint4*)(Bhi + (size_t)n * K + k0))[bc4];
                sbl[i] = ((const uint4*)(Blo + (size_t)n * K + k0))[bc4];
            } else {
                sbh[i] = make_uint4(0,0,0,0);
                sbl[i] = make_uint4(0,0,0,0);
            }
        }
    };
    // ---- store staged regs into smem buffer ----
    auto S = [&](int buf) {
        const uint32_t bb = sb + buf * 32768;
        #pragma unroll
        for (int i = 0; i < 4; i++) {
            float4 v = sa[i];
            __nv_bfloat162 h01 = __floats2bfloat162_rn(v.x, v.y);
            __nv_bfloat162 h23 = __floats2bfloat162_rn(v.z, v.w);
            float2 f01 = __bfloat1622float2(h01);
            float2 f23 = __bfloat1622float2(h23);
            __nv_bfloat162 l01 = __floats2bfloat162_rn(v.x - f01.x, v.y - f01.y);
            __nv_bfloat162 l23 = __floats2bfloat162_rn(v.z - f23.x, v.w - f23.y);
            uint32_t off = SWZ64((uint32_t)((ar + i * 32) * 64 + ac4 * 8));
            asm volatile("st.shared.v2.b32 [%0], {%1, %2};"
                :: "r"(bb + off), "r"(*(uint32_t*)&h01), "r"(*(uint32_t*)&h23));
            asm volatile("st.shared.v2.b32 [%0], {%1, %2};"
                :: "r"(bb + 8192 + off), "r"(*(uint32_t*)&l01), "r"(*(uint32_t*)&l23));
        }
        #pragma unroll
        for (int i = 0; i < 2; i++) {
            uint32_t off = SWZ64((uint32_t)((br + i * 64) * 64 + bc4 * 16));
            uint4 vh = sbh[i], vl = sbl[i];
            asm volatile("st.shared.v4.b32 [%0], {%1, %2, %3, %4};"
                :: "r"(bb + 16384 + off), "r"(vh.x), "r"(vh.y), "r"(vh.z), "r"(vh.w));
            asm volatile("st.shared.v4.b32 [%0], {%1, %2, %3, %4};"
                :: "r"(bb + 24576 + off), "r"(vl.x), "r"(vl.y), "r"(vl.z), "r"(vl.w));
        }
    };

    G(0);
    S(0);
    __syncthreads();

    for (int t = 0; t < T; t++) {
        const int buf = t & 1;
        const uint32_t bb = sb + buf * 32768;

        if (t + 1 < T) G(t + 1);   // issue next-tile global loads

        // ---- MMA on current buffer ----
        #pragma unroll
        for (int kk = 0; kk < 2; kk++) {
            const uint32_t kb = kk * 32 + ((lane >> 4) << 4);
            uint32_t ah[4][4], al[4][4];
            #pragma unroll
            for (int mi = 0; mi < 4; mi++) {
                uint32_t addr = bb + SWZ64((uint32_t)((wm + mi * 16 + (lane & 15)) * 64) + kb);
                ldm_x4(addr, ah[mi]);
                ldm_x4(addr + 8192, al[mi]);
            }
            uint32_t bh[4][2], bl[4][2];
            #pragma unroll
            for (int np = 0; np < 2; np++) {
                uint32_t addr = bb + 16384 +
                    SWZ64((uint32_t)((wn + np * 16 + (lane & 15)) * 64) + kb);
                uint32_t q[4];
                ldm_x4(addr, q);
                bh[2*np][0] = q[0]; bh[2*np][1] = q[2];
                bh[2*np+1][0] = q[1]; bh[2*np+1][1] = q[3];
                ldm_x4(addr + 8192, q);
                bl[2*np][0] = q[0]; bl[2*np][1] = q[2];
                bl[2*np+1][0] = q[1]; bl[2*np+1][1] = q[3];
            }
            #pragma unroll
            for (int mi = 0; mi < 4; mi++)
                #pragma unroll
                for (int ni = 0; ni < 4; ni++) {
                    mma16816(acc[mi][ni], ah[mi], bh[ni][0], bh[ni][1]);
                    mma16816(acc[mi][ni], ah[mi], bl[ni][0], bl[ni][1]);
                    mma16816(acc[mi][ni], al[mi], bh[ni][0], bh[ni][1]);
                }
        }
        __syncthreads();
        if (t + 1 < T) {
            S(buf ^ 1);
            __syncthreads();
        }
    }

    // ---- epilogue: direct float2 stores ----
    const int r0 = lane >> 2, c0 = (lane & 3) * 2;
    #pragma unroll
    for (int mi = 0; mi < 4; mi++) {
        #pragma unroll
        for (int ni = 0; ni < 4; ni++) {
            int row = m0 + wm + mi * 16 + r0;
            int col = n0 + wn + ni * 8 + c0;
            if (col < N) {
                *(float2*)(C + (size_t)row * ldc + col) =
                    make_float2(acc[mi][ni][0], acc[mi][ni][1]);
                *(float2*)(C + (size_t)(row + 8) * ldc + col) =
                    make_float2(acc[mi][ni][2], acc[mi][ni][3]);
            }
        }
    }
}

// =====================================================================
// RoPE (unchanged)
// =====================================================================
__global__ void rope_kernel(float* __restrict__ q, float* __restrict__ ckv,
                            const int* __restrict__ position)
{
    int idx = blockIdx.x * blockDim.x + threadIdx.x;
    const int total = BS * 17 * 32;
    if (idx >= total) return;
    int j = idx & 31;
    int rest = idx >> 5;
    int h = rest % 17;
    int bs = rest / 17;
    int s = bs & (SEQ - 1);

    float pos = (float)position[s];
    float inv = __expf(-(float)(2 * j) * (9.210340371976184f / 64.0f));
    float ang = pos * inv;
    float sn, cs;
    sincosf(ang, &sn, &cs);

    float* base = (h < 16)
        ? (q + (size_t)bs * QW + h * QH + NOPE)
        : (ckv + (size_t)bs * CKV_W + KVL);
    float t1 = base[j];
    float t2 = base[j + 32];
    base[j]      = t1 * cs - t2 * sn;
    base[j + 32] = t2 * cs + t1 * sn;
}

// =====================================================================
// Flash attention (unchanged SIMT fp32)
// =====================================================================
#define ATTN_SMEM_FLOATS (64*196 + 32*196 + 32*128 + 64*33)
#define ATTN_SMEM_BYTES  (ATTN_SMEM_FLOATS * 4)

__global__ __launch_bounds__(256)
void attn_kernel(const float* __restrict__ q, const float* __restrict__ kv,
                 const float* __restrict__ ckv, float* __restrict__ out)
{
    extern __shared__ float smf[];
    float* Qs = smf;
    float* Ks = Qs + 64 * 196;
    float* Vs = Ks + 32 * 196;
    float* Ps = Vs + 32 * 128;

    const int b  = blockIdx.z;
    const int h  = blockIdx.y;
    const int q0 = blockIdx.x * 64;
    const int tid = threadIdx.x;
    const int tx = tid & 15, ty = tid >> 4;

    const float* qbase = q + (size_t)(b * SEQ + q0) * QW + h * QH;
    for (int i = tid; i < 64 * 48; i += 256) {
        int r = i / 48, c4 = i % 48;
        ((float4*)(Qs + r * 196))[c4] = ((const float4*)(qbase + (size_t)r * QW))[c4];
    }

    float mrow[4], lrow[4], acc[4][8];
    #pragma unroll
    for (int i = 0; i < 4; i++) {
        mrow[i] = -1e30f; lrow[i] = 0.f;
        #pragma unroll
        for (int j = 0; j < 8; j++) acc[i][j] = 0.f;
    }
    const float scale = 0.07216878364870323f;

    for (int kt = 0; kt < SEQ / 32; kt++) {
        __syncthreads();
        for (int i = tid; i < 32 * 48; i += 256) {
            int r = i / 48, c4 = i % 48;
            size_t row = (size_t)(b * SEQ + kt * 32 + r);
            float4 v;
            if (c4 < 32) v = ((const float4*)(kv + row * KVW + h * 256))[c4];
            else         v = ((const float4*)(ckv + row * CKV_W + KVL))[c4 - 32];
            ((float4*)(Ks + r * 196))[c4] = v;
        }
        for (int i = tid; i < 32 * 32; i += 256) {
            int r = i >> 5, c4 = i & 31;
            ((float4*)(Vs + r * 128))[c4] =
                ((const float4*)(kv + (size_t)(b * SEQ + kt * 32 + r) * KVW + h * 256 + NOPE))[c4];
        }
        __syncthreads();

        float s0[4] = {0.f, 0.f, 0.f, 0.f};
        float s1[4] = {0.f, 0.f, 0.f, 0.f};
        const float4* kb0 = (const float4*)(Ks + tx * 196);
        const float4* kb1 = (const float4*)(Ks + (tx + 16) * 196);
        #pragma unroll 4
        for (int d4 = 0; d4 < 48; d4++) {
            float4 ka = kb0[d4];
            float4 kc = kb1[d4];
            #pragma unroll
            for (int i = 0; i < 4; i++) {
                float4 qv = ((const float4*)(Qs + (ty * 4 + i) * 196))[d4];
                s0[i] += qv.x * ka.x + qv.y * ka.y + qv.z * ka.z + qv.w * ka.w;
                s1[i] += qv.x * kc.x + qv.y * kc.y + qv.z * kc.z + qv.w * kc.w;
            }
        }

        #pragma unroll
        for (int i = 0; i < 4; i++) {
            float a = s0[i] * scale;
            float c = s1[i] * scale;
            float rm = fmaxf(a, c);
            #pragma unroll
            for (int off = 8; off; off >>= 1)
                rm = fmaxf(rm, __shfl_xor_sync(0xffffffffu, rm, off));
            float mnew  = fmaxf(mrow[i], rm);
            float alpha = __expf(mrow[i] - mnew);
            float p0 = __expf(a - mnew);
            float p1 = __expf(c - mnew);
            float rs = p0 + p1;
            #pragma unroll
            for (int off = 8; off; off >>= 1)
                rs += __shfl_xor_sync(0xffffffffu, rs, off);
            lrow[i] = lrow[i] * alpha + rs;
            mrow[i] = mnew;
            #pragma unroll
            for (int j = 0; j < 8; j++) acc[i][j] *= alpha;
            Ps[(ty * 4 + i) * 33 + tx]      = p0;
            Ps[(ty * 4 + i) * 33 + tx + 16] = p1;
        }
        __syncthreads();

        #pragma unroll 4
        for (int k = 0; k < 32; k++) {
            float4 v0 = ((const float4*)(Vs + k * 128))[tx];
            float4 v1 = ((const float4*)(Vs + k * 128))[tx + 16];
            #pragma unroll
            for (int i = 0; i < 4; i++) {
                float p = Ps[(ty * 4 + i) * 33 + k];
                acc[i][0] += p * v0.x; acc[i][1] += p * v0.y;
                acc[i][2] += p * v0.z; acc[i][3] += p * v0.w;
                acc[i][4] += p * v1.x; acc[i][5] += p * v1.y;
                acc[i][6] += p * v1.z; acc[i][7] += p * v1.w;
            }
        }
    }

    #pragma unroll
    for (int i = 0; i < 4; i++) {
        float inv = 1.0f / lrow[i];
        float4 o0 = make_float4(acc[i][0]*inv, acc[i][1]*inv, acc[i][2]*inv, acc[i][3]*inv);
        float4 o1 = make_float4(acc[i][4]*inv, acc[i][5]*inv, acc[i][6]*inv, acc[i][7]*inv);
        float* ob = out + (size_t)(b * SEQ + q0 + ty * 4 + i) * HID + h * VH;
        ((float4*)ob)[tx]      = o0;
        ((float4*)ob)[tx + 16] = o1;
    }
}

// =====================================================================
extern "C" void kernel_launch(void* const* d_in, const int* in_sizes, int n_in,
                              void* d_out, int out_size)
{
    const float* x        = (const float*)d_in[0];
    const int*   position = (const int*)  d_in[1];
    const float* Wq_down  = (const float*)d_in[2];
    const float* Wq_up    = (const float*)d_in[3];
    const float* Wkv_down = (const float*)d_in[4];
    const float* Wkv_up   = (const float*)d_in[5];
    const float* Wout     = (const float*)d_in[6];
    float*       out      = (float*)d_out;

    float *cq, *qb, *ckv, *kvb, *attn;
    __nv_bfloat16* w;
    cudaGetSymbolAddress((void**)&cq,   g_cq);
    cudaGetSymbolAddress((void**)&qb,   g_q);
    cudaGetSymbolAddress((void**)&ckv,  g_ckv);
    cudaGetSymbolAddress((void**)&kvb,  g_kv);
    cudaGetSymbolAddress((void**)&attn, g_attn);
    cudaGetSymbolAddress((void**)&w,    g_w);

    cudaFuncSetAttribute(attn_kernel, cudaFuncAttributeMaxDynamicSharedMemorySize,
                         ATTN_SMEM_BYTES);
    cudaFuncSetAttribute(gemm_mma, cudaFuncAttributeMaxDynamicSharedMemorySize,
                         GEMM_SMEM);

    // ---- weight transpose + split ----
    wconv<<<dim3(1024/32, 2048/32), 256>>>(Wq_down,  w + O_WQD_HI, w + O_WQD_LO, 2048, 1024);
    wconv<<<dim3(3072/32, 1024/32), 256>>>(Wq_up,    w + O_WQU_HI, w + O_WQU_LO, 1024, 3072);
    wconv<<<dim3(576/32,  2048/32), 256>>>(Wkv_down, w + O_WKD_HI, w + O_WKD_LO, 2048, 576);
    wconv<<<dim3(4096/32, 512/32),  256>>>(Wkv_up,   w + O_WKU_HI, w + O_WKU_LO, 512,  4096);
    wconv<<<dim3(2048/32, 2048/32), 256>>>(Wout,     w + O_WO_HI,  w + O_WO_LO,  2048, 2048);

    // ---- GEMMs on tensor cores (mma.sync) ----
    gemm_mma<<<dim3(QLORA/128, BS/128), 256, GEMM_SMEM>>>(
        x, w + O_WQD_HI, w + O_WQD_LO, cq, BS, QLORA, HID, HID, QLORA);
    gemm_mma<<<dim3(QW/128, BS/128), 256, GEMM_SMEM>>>(
        cq, w + O_WQU_HI, w + O_WQU_LO, qb, BS, QW, QLORA, QLORA, QW);
    gemm_mma<<<dim3((CKV_W + 127)/128, BS/128), 256, GEMM_SMEM>>>(
        x, w + O_WKD_HI, w + O_WKD_LO, ckv, BS, CKV_W, HID, HID, CKV_W);

    rope_kernel<<<(BS*17*32 + 255)/256, 256>>>(qb, ckv, position);

    gemm_mma<<<dim3(KVW/128, BS/128), 256, GEMM_SMEM>>>(
        ckv, w + O_WKU_HI, w + O_WKU_LO, kvb, BS, KVW, KVL, CKV_W, KVW);

    attn_kernel<<<dim3(SEQ/64, HEADS, BATCH), 256, ATTN_SMEM_BYTES>>>(qb, kvb, ckv, attn);

    gemm_mma<<<dim3(HID/128, BS/128), 256, GEMM_SMEM>>>(
        attn, w + O_WO_HI, w + O_WO_LO, out, BS, HID, HID, HID, HID);
}

// round 4
// speedup vs baseline: 4.0116x; 3.0482x over previous
#include <cuda_runtime.h>
#include <cuda_bf16.h>
#include <cuda_fp16.h>
#include <math.h>
#include <stdint.h>

// ---------------- problem dims ----------------
#define HID     2048
#define HEADS   16
#define SEQ     2048
#define BATCH   2
#define BS      (BATCH*SEQ)          // 4096
#define QLORA   1024
#define QH      192
#define NOPE    128
#define ROPED   64
#define VH      128
#define KVL     512
#define CKV_W   576
#define QW      (HEADS*QH)           // 3072
#define KVW     (HEADS*(NOPE+VH))    // 4096

// ---------------- scratch ----------------
__device__ float g_cq  [(size_t)BS * QLORA];
__device__ float g_q   [(size_t)BS * QW];
__device__ float g_ckv [(size_t)BS * CKV_W];
__device__ float g_kv  [(size_t)BS * KVW];
__device__ float g_attn[(size_t)BS * HID];
// fp16 packed attention operands
__device__ __half g_q16[(size_t)BS * QW];
__device__ __half g_k16[(size_t)BS * HEADS * QH];
__device__ __half g_v16[(size_t)BS * HEADS * VH];
// transposed + hi/lo split bf16 weights
#define WQD_SZ  (1024*2048)
#define WQU_SZ  (3072*1024)
#define WKD_SZ  (576*2048)
#define WKU_SZ  (4096*512)
#define WO_SZ   (2048*2048)
#define O_WQD_HI 0
#define O_WQD_LO (O_WQD_HI + WQD_SZ)
#define O_WQU_HI (O_WQD_LO + WQD_SZ)
#define O_WQU_LO (O_WQU_HI + WQU_SZ)
#define O_WKD_HI (O_WQU_LO + WQU_SZ)
#define O_WKD_LO (O_WKD_HI + WKD_SZ)
#define O_WKU_HI (O_WKD_LO + WKD_SZ)
#define O_WKU_LO (O_WKU_HI + WKU_SZ)
#define O_WO_HI  (O_WKU_LO + WKU_SZ)
#define O_WO_LO  (O_WO_HI + WO_SZ)
#define W_TOTAL  (O_WO_LO + WO_SZ)
__device__ __nv_bfloat16 g_w[W_TOTAL];

// ---------------- helpers ----------------
__device__ __forceinline__ uint32_t smem_u32(const void* p) {
    uint32_t a;
    asm("{ .reg .u64 t; cvta.to.shared.u64 t, %1; cvt.u32.u64 %0, t; }"
        : "=r"(a) : "l"(p));
    return a;
}
#define SWZ64(o) ((o) ^ (((o) >> 3) & 0x30))

__device__ __forceinline__ void ldm_x4(uint32_t addr, uint32_t r[4]) {
    asm volatile("ldmatrix.sync.aligned.m8n8.x4.shared.b16 {%0,%1,%2,%3}, [%4];"
                 : "=r"(r[0]), "=r"(r[1]), "=r"(r[2]), "=r"(r[3]) : "r"(addr));
}
__device__ __forceinline__ void ldm_x4_t(uint32_t addr, uint32_t r[4]) {
    asm volatile("ldmatrix.sync.aligned.m8n8.x4.trans.shared.b16 {%0,%1,%2,%3}, [%4];"
                 : "=r"(r[0]), "=r"(r[1]), "=r"(r[2]), "=r"(r[3]) : "r"(addr));
}
__device__ __forceinline__ void mma16816(float d[4], const uint32_t a[4],
                                         const uint32_t b0, const uint32_t b1) {
    asm volatile("mma.sync.aligned.m16n8k16.row.col.f32.bf16.bf16.f32 "
                 "{%0,%1,%2,%3}, {%4,%5,%6,%7}, {%8,%9}, {%0,%1,%2,%3};"
                 : "+f"(d[0]), "+f"(d[1]), "+f"(d[2]), "+f"(d[3])
                 : "r"(a[0]), "r"(a[1]), "r"(a[2]), "r"(a[3]), "r"(b0), "r"(b1));
}
__device__ __forceinline__ void mma_f16(float d[4], const uint32_t a[4],
                                        const uint32_t b0, const uint32_t b1) {
    asm volatile("mma.sync.aligned.m16n8k16.row.col.f32.f16.f16.f32 "
                 "{%0,%1,%2,%3}, {%4,%5,%6,%7}, {%8,%9}, {%0,%1,%2,%3};"
                 : "+f"(d[0]), "+f"(d[1]), "+f"(d[2]), "+f"(d[3])
                 : "r"(a[0]), "r"(a[1]), "r"(a[2]), "r"(a[3]), "r"(b0), "r"(b1));
}
__device__ __forceinline__ uint32_t packh2(float lo, float hi) {
    uint32_t d;
    asm("cvt.rn.f16x2.f32 %0, %1, %2;" : "=r"(d) : "f"(hi), "f"(lo));
    return d;
}
#define CPA(s, g) asm volatile("cp.async.cg.shared.global [%0], [%1], 16;" :: "r"(s), "l"(g))

// =====================================================================
// Weight transpose + hi/lo bf16 split: W[K,N] -> Whi/Wlo[N,K]
// =====================================================================
__global__ __launch_bounds__(256)
void wconv(const float* __restrict__ W, __nv_bfloat16* __restrict__ hi,
           __nv_bfloat16* __restrict__ lo, int K, int N)
{
    __shared__ float t[32][33];
    int n0 = blockIdx.x * 32, k0 = blockIdx.y * 32;
    int tx = threadIdx.x & 31, ty = threadIdx.x >> 5;
    #pragma unroll
    for (int j = 0; j < 4; j++)
        t[ty + 8*j][tx] = W[(size_t)(k0 + ty + 8*j) * N + n0 + tx];
    __syncthreads();
    #pragma unroll
    for (int j = 0; j < 4; j++) {
        float v = t[tx][ty + 8*j];
        __nv_bfloat16 h = __float2bfloat16(v);
        __nv_bfloat16 l = __float2bfloat16(v - __bfloat162float(h));
        size_t o = (size_t)(n0 + ty + 8*j) * K + k0 + tx;
        hi[o] = h;
        lo[o] = l;
    }
}

// =====================================================================
// mma.sync bf16 hi/lo-split GEMM (unchanged from R3)
// =====================================================================
#define GEMM_SMEM 65536

__global__ __launch_bounds__(256, 1)
void gemm_mma(const float* __restrict__ A,
              const __nv_bfloat16* __restrict__ Bhi,
              const __nv_bfloat16* __restrict__ Blo,
              float* __restrict__ C,
              int M, int N, int K, int lda, int ldc)
{
    extern __shared__ char sm[];
    const uint32_t sb = smem_u32(sm);
    const int tid  = threadIdx.x;
    const int lane = tid & 31;
    const int wid  = tid >> 5;
    const int wm   = (wid >> 2) * 64;
    const int wn   = (wid & 3) * 32;
    const int m0   = blockIdx.y * 128;
    const int n0   = blockIdx.x * 128;

    float acc[4][4][4];
    #pragma unroll
    for (int i = 0; i < 4; i++)
        #pragma unroll
        for (int j = 0; j < 4; j++)
            #pragma unroll
            for (int c = 0; c < 4; c++) acc[i][j][c] = 0.f;

    float4 sa[4];
    uint4  sbh[2], sbl[2];

    const int T = K >> 5;
    const int ar = tid >> 3, ac4 = tid & 7;
    const int br = tid >> 2, bc4 = tid & 3;

    auto G = [&](int t) {
        const int k0 = t << 5;
        #pragma unroll
        for (int i = 0; i < 4; i++)
            sa[i] = *(const float4*)(A + (size_t)(m0 + ar + i * 32) * lda + k0 + ac4 * 4);
        #pragma unroll
        for (int i = 0; i < 2; i++) {
            int n = n0 + br + i * 64;
            if (n < N) {
                sbh[i] = ((const uint4*)(Bhi + (size_t)n * K + k0))[bc4];
                sbl[i] = ((const uint4*)(Blo + (size_t)n * K + k0))[bc4];
            } else {
                sbh[i] = make_uint4(0,0,0,0);
                sbl[i] = make_uint4(0,0,0,0);
            }
        }
    };
    auto S = [&](int buf) {
        const uint32_t bb = sb + buf * 32768;
        #pragma unroll
        for (int i = 0; i < 4; i++) {
            float4 v = sa[i];
            __nv_bfloat162 h01 = __floats2bfloat162_rn(v.x, v.y);
            __nv_bfloat162 h23 = __floats2bfloat162_rn(v.z, v.w);
            float2 f01 = __bfloat1622float2(h01);
            float2 f23 = __bfloat1622float2(h23);
            __nv_bfloat162 l01 = __floats2bfloat162_rn(v.x - f01.x, v.y - f01.y);
            __nv_bfloat162 l23 = __floats2bfloat162_rn(v.z - f23.x, v.w - f23.y);
            uint32_t off = SWZ64((uint32_t)((ar + i * 32) * 64 + ac4 * 8));
            asm volatile("st.shared.v2.b32 [%0], {%1, %2};"
                :: "r"(bb + off), "r"(*(uint32_t*)&h01), "r"(*(uint32_t*)&h23));
            asm volatile("st.shared.v2.b32 [%0], {%1, %2};"
                :: "r"(bb + 8192 + off), "r"(*(uint32_t*)&l01), "r"(*(uint32_t*)&l23));
        }
        #pragma unroll
        for (int i = 0; i < 2; i++) {
            uint32_t off = SWZ64((uint32_t)((br + i * 64) * 64 + bc4 * 16));
            uint4 vh = sbh[i], vl = sbl[i];
            asm volatile("st.shared.v4.b32 [%0], {%1, %2, %3, %4};"
                :: "r"(bb + 16384 + off), "r"(vh.x), "r"(vh.y), "r"(vh.z), "r"(vh.w));
            asm volatile("st.shared.v4.b32 [%0], {%1, %2, %3, %4};"
                :: "r"(bb + 24576 + off), "r"(vl.x), "r"(vl.y), "r"(vl.z), "r"(vl.w));
        }
    };

    G(0);
    S(0);
    __syncthreads();

    for (int t = 0; t < T; t++) {
        const int buf = t & 1;
        const uint32_t bb = sb + buf * 32768;

        if (t + 1 < T) G(t + 1);

        #pragma unroll
        for (int kk = 0; kk < 2; kk++) {
            const uint32_t kb = kk * 32 + ((lane >> 4) << 4);
            uint32_t ah[4][4], al[4][4];
            #pragma unroll
            for (int mi = 0; mi < 4; mi++) {
                uint32_t addr = bb + SWZ64((uint32_t)((wm + mi * 16 + (lane & 15)) * 64) + kb);
                ldm_x4(addr, ah[mi]);
                ldm_x4(addr + 8192, al[mi]);
            }
            uint32_t bh[4][2], bl[4][2];
            #pragma unroll
            for (int np = 0; np < 2; np++) {
                uint32_t addr = bb + 16384 +
                    SWZ64((uint32_t)((wn + np * 16 + (lane & 15)) * 64) + kb);
                uint32_t q[4];
                ldm_x4(addr, q);
                bh[2*np][0] = q[0]; bh[2*np][1] = q[2];
                bh[2*np+1][0] = q[1]; bh[2*np+1][1] = q[3];
                ldm_x4(addr + 8192, q);
                bl[2*np][0] = q[0]; bl[2*np][1] = q[2];
                bl[2*np+1][0] = q[1]; bl[2*np+1][1] = q[3];
            }
            #pragma unroll
            for (int mi = 0; mi < 4; mi++)
                #pragma unroll
                for (int ni = 0; ni < 4; ni++) {
                    mma16816(acc[mi][ni], ah[mi], bh[ni][0], bh[ni][1]);
                    mma16816(acc[mi][ni], ah[mi], bl[ni][0], bl[ni][1]);
                    mma16816(acc[mi][ni], al[mi], bh[ni][0], bh[ni][1]);
                }
        }
        __syncthreads();
        if (t + 1 < T) {
            S(buf ^ 1);
            __syncthreads();
        }
    }

    const int r0 = lane >> 2, c0 = (lane & 3) * 2;
    #pragma unroll
    for (int mi = 0; mi < 4; mi++) {
        #pragma unroll
        for (int ni = 0; ni < 4; ni++) {
            int row = m0 + wm + mi * 16 + r0;
            int col = n0 + wn + ni * 8 + c0;
            if (col < N) {
                *(float2*)(C + (size_t)row * ldc + col) =
                    make_float2(acc[mi][ni][0], acc[mi][ni][1]);
                *(float2*)(C + (size_t)(row + 8) * ldc + col) =
                    make_float2(acc[mi][ni][2], acc[mi][ni][3]);
            }
        }
    }
}

// =====================================================================
// RoPE (unchanged)
// =====================================================================
__global__ void rope_kernel(float* __restrict__ q, float* __restrict__ ckv,
                            const int* __restrict__ position)
{
    int idx = blockIdx.x * blockDim.x + threadIdx.x;
    const int total = BS * 17 * 32;
    if (idx >= total) return;
    int j = idx & 31;
    int rest = idx >> 5;
    int h = rest % 17;
    int bs = rest / 17;
    int s = bs & (SEQ - 1);

    float pos = (float)position[s];
    float inv = __expf(-(float)(2 * j) * (9.210340371976184f / 64.0f));
    float ang = pos * inv;
    float sn, cs;
    sincosf(ang, &sn, &cs);

    float* base = (h < 16)
        ? (q + (size_t)bs * QW + h * QH + NOPE)
        : (ckv + (size_t)bs * CKV_W + KVL);
    float t1 = base[j];
    float t2 = base[j + 32];
    base[j]      = t1 * cs - t2 * sn;
    base[j + 32] = t2 * cs + t1 * sn;
}

// =====================================================================
// fp32 -> fp16 packing for attention: q16[bs][h][192], k16[bs][h][192]
// (nope from kv, rope from ckv), v16[bs][h][128]
// =====================================================================
__global__ __launch_bounds__(256)
void cvt16(const float* __restrict__ q, const float* __restrict__ kv,
           const float* __restrict__ ckv,
           __half* __restrict__ q16, __half* __restrict__ k16,
           __half* __restrict__ v16)
{
    const int bs = blockIdx.x;
    const int tid = threadIdx.x;

    const float2* qs = (const float2*)(q + (size_t)bs * QW);
    __half2* qd = (__half2*)(q16 + (size_t)bs * QW);
    #pragma unroll 2
    for (int i = tid; i < 1536; i += 256)
        qd[i] = __float22half2_rn(qs[i]);

    const float* kvb = kv + (size_t)bs * KVW;
    __half2* vd = (__half2*)(v16 + (size_t)bs * (HEADS * VH));
    #pragma unroll 2
    for (int i = tid; i < 1024; i += 256) {
        int h = i >> 6, d2 = i & 63;
        float2 vv = *(const float2*)(kvb + h * 256 + 128 + d2 * 2);
        vd[i] = __float22half2_rn(vv);
    }

    __half2* kd = (__half2*)(k16 + (size_t)bs * (HEADS * QH));
    const float* ck = ckv + (size_t)bs * CKV_W + KVL;
    #pragma unroll 2
    for (int i = tid; i < 1536; i += 256) {
        int h = i / 96, dp = i % 96;
        float2 vv = (dp < 64) ? *(const float2*)(kvb + h * 256 + dp * 2)
                              : *(const float2*)(ck + (dp - 64) * 2);
        kd[i] = __float22half2_rn(vv);
    }
}

// =====================================================================
// Flash attention with fp16 mma.sync.
// grid (SEQ/64, HEADS, BATCH), 128 threads (4 warps, 16 q-rows each).
// BK=64 keys/iter, cp.async double-buffered K/V tiles.
// smem: 2 x (K 64x384B + V 64x256B) = 81920 B.
// =====================================================================
#define KBUF 24576
#define VBUF 16384
#define ABUF (KBUF + VBUF)
#define ATTN_SMEM (2 * ABUF)

__device__ __forceinline__ uint32_t kaddr(uint32_t base, int row, int db) {
    uint32_t within = (uint32_t)(db & 127) ^ (uint32_t)((row & 7) << 4);
    return base + row * 384 + (uint32_t)(db & ~127) + within;
}
__device__ __forceinline__ uint32_t vaddr(uint32_t base, int row, int db) {
    uint32_t within = (uint32_t)(db & 127) ^ (uint32_t)((row & 7) << 4);
    return base + row * 256 + (uint32_t)(db & ~127) + within;
}

__global__ __launch_bounds__(128)
void attn_mma(const __half* __restrict__ q16, const __half* __restrict__ k16,
              const __half* __restrict__ v16, float* __restrict__ out)
{
    extern __shared__ char sm[];
    const uint32_t sb = smem_u32(sm);
    const int b = blockIdx.z, h = blockIdx.y, q0 = blockIdx.x * 64;
    const int tid = threadIdx.x, lane = tid & 31, w = tid >> 5;

    // ---- prologue: Q tile -> buf0 K area, extract fragments ----
    #pragma unroll
    for (int i = 0; i < 12; i++) {
        int idx = tid + i * 128;
        int row = idx / 24, c16 = idx % 24;
        const char* g = (const char*)(q16 +
            ((size_t)(b * SEQ + q0 + row) * HEADS + h) * QH) + c16 * 16;
        CPA(kaddr(sb, row, c16 * 16), g);
    }
    asm volatile("cp.async.commit_group;");
    asm volatile("cp.async.wait_group 0;");
    __syncthreads();

    uint32_t qa[12][4];
    {
        int r = w * 16 + (lane & 15);
        int dhi = (lane >> 4) * 16;
        #pragma unroll
        for (int ks = 0; ks < 12; ks++)
            ldm_x4(kaddr(sb, r, ks * 32 + dhi), qa[ks]);
    }
    __syncthreads();

    // ---- K/V tile issuer ----
    auto issue = [&](int kt, int buf) {
        const uint32_t kb = sb + buf * ABUF;
        const uint32_t vb = kb + KBUF;
        const int key0 = kt * 64;
        #pragma unroll
        for (int i = 0; i < 12; i++) {
            int idx = tid + i * 128;
            int row = idx / 24, c16 = idx % 24;
            const char* g = (const char*)(k16 +
                ((size_t)(b * SEQ + key0 + row) * HEADS + h) * QH) + c16 * 16;
            CPA(kaddr(kb, row, c16 * 16), g);
        }
        #pragma unroll
        for (int i = 0; i < 8; i++) {
            int idx = tid + i * 128;
            int row = idx >> 4, c16 = idx & 15;
            const char* g = (const char*)(v16 +
                ((size_t)(b * SEQ + key0 + row) * HEADS + h) * VH) + c16 * 16;
            CPA(vaddr(vb, row, c16 * 16), g);
        }
        asm volatile("cp.async.commit_group;");
    };

    float o[16][4];
    #pragma unroll
    for (int i = 0; i < 16; i++)
        #pragma unroll
        for (int j = 0; j < 4; j++) o[i][j] = 0.f;
    float m0 = -1e30f, m1 = -1e30f, l0 = 0.f, l1 = 0.f;
    const float sc = 0.07216878364870323f;  // 1/sqrt(192)

    issue(0, 0);

    for (int kt = 0; kt < SEQ / 64; kt++) {
        if (kt + 1 < SEQ / 64) {
            issue(kt + 1, (kt + 1) & 1);
            asm volatile("cp.async.wait_group 1;");
        } else {
            asm volatile("cp.async.wait_group 0;");
        }
        __syncthreads();

        const uint32_t kb = sb + (kt & 1) * ABUF;
        const uint32_t vb = kb + KBUF;

        // ---- S = Q K^T : warp rows w*16..+16, keys 0..63 ----
        float s[8][4];
        #pragma unroll
        for (int i = 0; i < 8; i++)
            #pragma unroll
            for (int j = 0; j < 4; j++) s[i][j] = 0.f;

        const int krow_off = ((lane >> 4) << 3) + (lane & 7);
        const int kdim_off = ((lane >> 3) & 1) * 16;
        #pragma unroll
        for (int ks = 0; ks < 12; ks++) {
            #pragma unroll
            for (int kb4 = 0; kb4 < 4; kb4++) {
                uint32_t r[4];
                ldm_x4(kaddr(kb, kb4 * 16 + krow_off, ks * 32 + kdim_off), r);
                mma_f16(s[2 * kb4],     qa[ks], r[0], r[1]);
                mma_f16(s[2 * kb4 + 1], qa[ks], r[2], r[3]);
            }
        }

        // ---- online softmax ----
        float mx0 = -1e30f, mx1 = -1e30f;
        #pragma unroll
        for (int ni = 0; ni < 8; ni++) {
            mx0 = fmaxf(mx0, fmaxf(s[ni][0], s[ni][1]));
            mx1 = fmaxf(mx1, fmaxf(s[ni][2], s[ni][3]));
        }
        mx0 = fmaxf(mx0, __shfl_xor_sync(0xffffffffu, mx0, 1));
        mx0 = fmaxf(mx0, __shfl_xor_sync(0xffffffffu, mx0, 2));
        mx1 = fmaxf(mx1, __shfl_xor_sync(0xffffffffu, mx1, 1));
        mx1 = fmaxf(mx1, __shfl_xor_sync(0xffffffffu, mx1, 2));

        float mn0 = fmaxf(m0, mx0 * sc);
        float mn1 = fmaxf(m1, mx1 * sc);
        float a0 = __expf(m0 - mn0);
        float a1 = __expf(m1 - mn1);

        float rs0 = 0.f, rs1 = 0.f;
        uint32_t pa[4][4];
        #pragma unroll
        for (int ni = 0; ni < 8; ni++) {
            float p0 = __expf(s[ni][0] * sc - mn0);
            float p1 = __expf(s[ni][1] * sc - mn0);
            float p2 = __expf(s[ni][2] * sc - mn1);
            float p3 = __expf(s[ni][3] * sc - mn1);
            rs0 += p0 + p1;
            rs1 += p2 + p3;
            int kk = ni >> 1;
            if ((ni & 1) == 0) {
                pa[kk][0] = packh2(p0, p1);
                pa[kk][1] = packh2(p2, p3);
            } else {
                pa[kk][2] = packh2(p0, p1);
                pa[kk][3] = packh2(p2, p3);
            }
        }
        rs0 += __shfl_xor_sync(0xffffffffu, rs0, 1);
        rs0 += __shfl_xor_sync(0xffffffffu, rs0, 2);
        rs1 += __shfl_xor_sync(0xffffffffu, rs1, 1);
        rs1 += __shfl_xor_sync(0xffffffffu, rs1, 2);

        l0 = l0 * a0 + rs0;
        l1 = l1 * a1 + rs1;
        m0 = mn0; m1 = mn1;

        #pragma unroll
        for (int nj = 0; nj < 16; nj++) {
            o[nj][0] *= a0; o[nj][1] *= a0;
            o[nj][2] *= a1; o[nj][3] *= a1;
        }

        // ---- O += P V ----
        const int vrow_off = ((lane >> 3) & 1) * 8 + (lane & 7);
        const int vdim_off = (lane >> 4) * 16;
        #pragma unroll
        for (int kk = 0; kk < 4; kk++) {
            #pragma unroll
            for (int nb = 0; nb < 8; nb++) {
                uint32_t r[4];
                ldm_x4_t(vaddr(vb, kk * 16 + vrow_off, nb * 32 + vdim_off), r);
                mma_f16(o[2 * nb],     pa[kk], r[0], r[1]);
                mma_f16(o[2 * nb + 1], pa[kk], r[2], r[3]);
            }
        }
        __syncthreads();
    }

    // ---- normalize + store ----
    const float inv0 = 1.f / l0, inv1 = 1.f / l1;
    float* ob = out + (size_t)(b * SEQ + q0 + w * 16 + (lane >> 2)) * HID
                    + h * VH + (lane & 3) * 2;
    #pragma unroll
    for (int nj = 0; nj < 16; nj++) {
        *(float2*)(ob + nj * 8)            = make_float2(o[nj][0] * inv0, o[nj][1] * inv0);
        *(float2*)(ob + 8 * HID + nj * 8)  = make_float2(o[nj][2] * inv1, o[nj][3] * inv1);
    }
}

// =====================================================================
extern "C" void kernel_launch(void* const* d_in, const int* in_sizes, int n_in,
                              void* d_out, int out_size)
{
    const float* x        = (const float*)d_in[0];
    const int*   position = (const int*)  d_in[1];
    const float* Wq_down  = (const float*)d_in[2];
    const float* Wq_up    = (const float*)d_in[3];
    const float* Wkv_down = (const float*)d_in[4];
    const float* Wkv_up   = (const float*)d_in[5];
    const float* Wout     = (const float*)d_in[6];
    float*       out      = (float*)d_out;

    float *cq, *qb, *ckv, *kvb, *attn;
    __half *q16, *k16, *v16;
    __nv_bfloat16* w;
    cudaGetSymbolAddress((void**)&cq,   g_cq);
    cudaGetSymbolAddress((void**)&qb,   g_q);
    cudaGetSymbolAddress((void**)&ckv,  g_ckv);
    cudaGetSymbolAddress((void**)&kvb,  g_kv);
    cudaGetSymbolAddress((void**)&attn, g_attn);
    cudaGetSymbolAddress((void**)&q16,  g_q16);
    cudaGetSymbolAddress((void**)&k16,  g_k16);
    cudaGetSymbolAddress((void**)&v16,  g_v16);
    cudaGetSymbolAddress((void**)&w,    g_w);

    cudaFuncSetAttribute(gemm_mma, cudaFuncAttributeMaxDynamicSharedMemorySize,
                         GEMM_SMEM);
    cudaFuncSetAttribute(attn_mma, cudaFuncAttributeMaxDynamicSharedMemorySize,
                         ATTN_SMEM);

    // ---- weight transpose + split ----
    wconv<<<dim3(1024/32, 2048/32), 256>>>(Wq_down,  w + O_WQD_HI, w + O_WQD_LO, 2048, 1024);
    wconv<<<dim3(3072/32, 1024/32), 256>>>(Wq_up,    w + O_WQU_HI, w + O_WQU_LO, 1024, 3072);
    wconv<<<dim3(576/32,  2048/32), 256>>>(Wkv_down, w + O_WKD_HI, w + O_WKD_LO, 2048, 576);
    wconv<<<dim3(4096/32, 512/32),  256>>>(Wkv_up,   w + O_WKU_HI, w + O_WKU_LO, 512,  4096);
    wconv<<<dim3(2048/32, 2048/32), 256>>>(Wout,     w + O_WO_HI,  w + O_WO_LO,  2048, 2048);

    // ---- GEMMs ----
    gemm_mma<<<dim3(QLORA/128, BS/128), 256, GEMM_SMEM>>>(
        x, w + O_WQD_HI, w + O_WQD_LO, cq, BS, QLORA, HID, HID, QLORA);
    gemm_mma<<<dim3(QW/128, BS/128), 256, GEMM_SMEM>>>(
        cq, w + O_WQU_HI, w + O_WQU_LO, qb, BS, QW, QLORA, QLORA, QW);
    gemm_mma<<<dim3((CKV_W + 127)/128, BS/128), 256, GEMM_SMEM>>>(
        x, w + O_WKD_HI, w + O_WKD_LO, ckv, BS, CKV_W, HID, HID, CKV_W);

    rope_kernel<<<(BS*17*32 + 255)/256, 256>>>(qb, ckv, position);

    gemm_mma<<<dim3(KVW/128, BS/128), 256, GEMM_SMEM>>>(
        ckv, w + O_WKU_HI, w + O_WKU_LO, kvb, BS, KVW, KVL, CKV_W, KVW);

    cvt16<<<BS, 256>>>(qb, kvb, ckv, q16, k16, v16);

    attn_mma<<<dim3(SEQ/64, HEADS, BATCH), 128, ATTN_SMEM>>>(q16, k16, v16, attn);

    gemm_mma<<<dim3(HID/128, BS/128), 256, GEMM_SMEM>>>(
        attn, w + O_WO_HI, w + O_WO_LO, out, BS, HID, HID, HID, HID);
}

// round 5
// speedup vs baseline: 5.4438x; 1.3570x over previous
#include <cuda_runtime.h>
#include <cuda_fp16.h>
#include <math.h>
#include <stdint.h>

// ---------------- problem dims ----------------
#define HID     2048
#define HEADS   16
#define SEQ     2048
#define BATCH   2
#define BS      (BATCH*SEQ)          // 4096
#define QLORA   1024
#define QH      192
#define NOPE    128
#define ROPED   64
#define VH      128
#define KVL     512
#define CKV_W   576
#define QW      (HEADS*QH)           // 3072
#define KVW     (HEADS*(NOPE+VH))    // 4096

// ---------------- scratch (all fp16 intermediates) ----------------
__device__ __half g_x16 [(size_t)BS * HID];
__device__ __half g_cq  [(size_t)BS * QLORA];
__device__ __half g_q   [(size_t)BS * QW];
__device__ __half g_ckv [(size_t)BS * CKV_W];
__device__ __half g_kv  [(size_t)BS * KVW];
__device__ __half g_attn[(size_t)BS * HID];
// transposed + hi/lo split fp16 weights
#define WQD_SZ  (1024*2048)
#define WQU_SZ  (3072*1024)
#define WKD_SZ  (576*2048)
#define WKU_SZ  (4096*512)
#define WO_SZ   (2048*2048)
#define O_WQD_HI 0
#define O_WQD_LO (O_WQD_HI + WQD_SZ)
#define O_WQU_HI (O_WQD_LO + WQD_SZ)
#define O_WQU_LO (O_WQU_HI + WQU_SZ)
#define O_WKD_HI (O_WQU_LO + WQU_SZ)
#define O_WKD_LO (O_WKD_HI + WKD_SZ)
#define O_WKU_HI (O_WKD_LO + WKD_SZ)
#define O_WKU_LO (O_WKU_HI + WKU_SZ)
#define O_WO_HI  (O_WKU_LO + WKU_SZ)
#define O_WO_LO  (O_WO_HI + WO_SZ)
#define W_TOTAL  (O_WO_LO + WO_SZ)
__device__ __half g_w[W_TOTAL];

// ---------------- helpers ----------------
__device__ __forceinline__ uint32_t smem_u32(const void* p) {
    uint32_t a;
    asm("{ .reg .u64 t; cvta.to.shared.u64 t, %1; cvt.u32.u64 %0, t; }"
        : "=r"(a) : "l"(p));
    return a;
}
__device__ __forceinline__ void ldm_x4(uint32_t addr, uint32_t r[4]) {
    asm volatile("ldmatrix.sync.aligned.m8n8.x4.shared.b16 {%0,%1,%2,%3}, [%4];"
                 : "=r"(r[0]), "=r"(r[1]), "=r"(r[2]), "=r"(r[3]) : "r"(addr));
}
__device__ __forceinline__ void ldm_x4_t(uint32_t addr, uint32_t r[4]) {
    asm volatile("ldmatrix.sync.aligned.m8n8.x4.trans.shared.b16 {%0,%1,%2,%3}, [%4];"
                 : "=r"(r[0]), "=r"(r[1]), "=r"(r[2]), "=r"(r[3]) : "r"(addr));
}
__device__ __forceinline__ void mma_f16(float d[4], const uint32_t a[4],
                                        const uint32_t b0, const uint32_t b1) {
    asm volatile("mma.sync.aligned.m16n8k16.row.col.f32.f16.f16.f32 "
                 "{%0,%1,%2,%3}, {%4,%5,%6,%7}, {%8,%9}, {%0,%1,%2,%3};"
                 : "+f"(d[0]), "+f"(d[1]), "+f"(d[2]), "+f"(d[3])
                 : "r"(a[0]), "r"(a[1]), "r"(a[2]), "r"(a[3]), "r"(b0), "r"(b1));
}
__device__ __forceinline__ uint32_t packh2(float lo, float hi) {
    uint32_t d;
    asm("cvt.rn.f16x2.f32 %0, %1, %2;" : "=r"(d) : "f"(hi), "f"(lo));
    return d;
}
#define CPA(s, g) asm volatile("cp.async.cg.shared.global [%0], [%1], 16;" :: "r"(s), "l"(g))
#define CPA_COMMIT() asm volatile("cp.async.commit_group;")
#define CPA_WAIT(n)  asm volatile("cp.async.wait_group %0;" :: "n"(n))

// 128-byte-row swizzle: bank phase = row&7
__device__ __forceinline__ uint32_t sw128(uint32_t base, int row, int db) {
    return base + row * 128 + (uint32_t)(db ^ ((row & 7) << 4));
}

// =====================================================================
// x fp32 -> fp16
// =====================================================================
__global__ __launch_bounds__(256)
void cvtx(const float* __restrict__ x, __half* __restrict__ x16)
{
    int i = blockIdx.x * 256 + threadIdx.x;
    float2 v = ((const float2*)x)[i];
    ((__half2*)x16)[i] = __float22half2_rn(v);
}

// =====================================================================
// Weight transpose + hi/lo fp16 split: W[K,N] -> Whi/Wlo[N,K]
// =====================================================================
__global__ __launch_bounds__(256)
void wconv(const float* __restrict__ W, __half* __restrict__ hi,
           __half* __restrict__ lo, int K, int N)
{
    __shared__ float t[32][33];
    int n0 = blockIdx.x * 32, k0 = blockIdx.y * 32;
    int tx = threadIdx.x & 31, ty = threadIdx.x >> 5;
    #pragma unroll
    for (int j = 0; j < 4; j++)
        t[ty + 8*j][tx] = W[(size_t)(k0 + ty + 8*j) * N + n0 + tx];
    __syncthreads();
    #pragma unroll
    for (int j = 0; j < 4; j++) {
        float v = t[tx][ty + 8*j];
        __half h = __float2half_rn(v);
        __half l = __float2half_rn(v - __half2float(h));
        size_t o = (size_t)(n0 + ty + 8*j) * K + k0 + tx;
        hi[o] = h;
        lo[o] = l;
    }
}

// =====================================================================
// fp16 2-pass GEMM: C[M,N] = A[M,K] @ (Bh + Bl)[K,N]
// A fp16 row-major; Bh/Bl pre-transposed fp16 [N,K].
// CTA 128x128, BK=64, 8 warps (2x4), warp tile 64x32.
// cp.async double-buffered: per buffer A 16K | Bh 16K | Bl 16K = 48KB.
// =====================================================================
#define GBUF 49152
#define GEMM_SMEM (2*GBUF)

__global__ __launch_bounds__(256, 2)
void gemm_f16(const __half* __restrict__ A,
              const __half* __restrict__ Bh,
              const __half* __restrict__ Bl,
              __half* __restrict__ C16, float* __restrict__ C32,
              int M, int N, int K, int lda, int ldc)
{
    extern __shared__ char sm[];
    const uint32_t sb = smem_u32(sm);
    const int tid  = threadIdx.x;
    const int lane = tid & 31;
    const int wid  = tid >> 5;
    const int wm   = (wid >> 2) * 64;
    const int wn   = (wid & 3) * 32;
    const int m0   = blockIdx.y * 128;
    const int n0   = blockIdx.x * 128;

    float acc[4][4][4];
    #pragma unroll
    for (int i = 0; i < 4; i++)
        #pragma unroll
        for (int j = 0; j < 4; j++)
            #pragma unroll
            for (int c = 0; c < 4; c++) acc[i][j][c] = 0.f;

    const int T = K >> 6;
    // load coords: A 1024 chunks (128 rows x 8), B 1024 chunks each
    const int arow = tid >> 1, ac = (tid & 1) * 4;   // 2 threads/row, 4 chunks each
    const int brow = tid >> 1, bc = (tid & 1) * 4;

    auto issue = [&](int t) {
        const uint32_t bb = sb + (t & 1) * GBUF;
        const int k0 = t << 6;
        const char* ga = (const char*)(A + (size_t)(m0 + arow) * lda + k0) + ac * 16;
        #pragma unroll
        for (int c = 0; c < 4; c++)
            CPA(sw128(bb, arow, (ac + c) * 16), ga + c * 16);
        int n = n0 + brow;
        if (n >= N) n = N - 1;
        const char* gh = (const char*)(Bh + (size_t)n * K + k0) + bc * 16;
        const char* gl = (const char*)(Bl + (size_t)n * K + k0) + bc * 16;
        #pragma unroll
        for (int c = 0; c < 4; c++) {
            CPA(sw128(bb + 16384, brow, (bc + c) * 16), gh + c * 16);
            CPA(sw128(bb + 32768, brow, (bc + c) * 16), gl + c * 16);
        }
        CPA_COMMIT();
    };

    issue(0);
    if (T > 1) issue(1);

    for (int t = 0; t < T; t++) {
        if (t + 1 < T) CPA_WAIT(1); else CPA_WAIT(0);
        __syncthreads();

        const uint32_t bb = sb + (t & 1) * GBUF;
        const int klo = (lane >> 4) << 4;   // 16B half-select within 32B k-step

        #pragma unroll
        for (int ks = 0; ks < 4; ks++) {
            uint32_t af[4][4];
            #pragma unroll
            for (int mi = 0; mi < 4; mi++)
                ldm_x4(sw128(bb, wm + mi * 16 + (lane & 15), ks * 32 + klo), af[mi]);
            uint32_t bhf[4][2], blf[4][2];
            #pragma unroll
            for (int np = 0; np < 2; np++) {
                uint32_t q[4];
                ldm_x4(sw128(bb + 16384, wn + np * 16 + (lane & 15), ks * 32 + klo), q);
                bhf[2*np][0] = q[0]; bhf[2*np][1] = q[2];
                bhf[2*np+1][0] = q[1]; bhf[2*np+1][1] = q[3];
                ldm_x4(sw128(bb + 32768, wn + np * 16 + (lane & 15), ks * 32 + klo), q);
                blf[2*np][0] = q[0]; blf[2*np][1] = q[2];
                blf[2*np+1][0] = q[1]; blf[2*np+1][1] = q[3];
            }
            #pragma unroll
            for (int mi = 0; mi < 4; mi++)
                #pragma unroll
                for (int ni = 0; ni < 4; ni++) {
                    mma_f16(acc[mi][ni], af[mi], bhf[ni][0], bhf[ni][1]);
                    mma_f16(acc[mi][ni], af[mi], blf[ni][0], blf[ni][1]);
                }
        }
        __syncthreads();
        if (t + 2 < T) issue(t + 2);
    }

    // ---- epilogue ----
    const int r0 = lane >> 2, c0 = (lane & 3) * 2;
    #pragma unroll
    for (int mi = 0; mi < 4; mi++) {
        #pragma unroll
        for (int ni = 0; ni < 4; ni++) {
            int row = m0 + wm + mi * 16 + r0;
            int col = n0 + wn + ni * 8 + c0;
            if (col < N) {
                if (C32) {
                    *(float2*)(C32 + (size_t)row * ldc + col) =
                        make_float2(acc[mi][ni][0], acc[mi][ni][1]);
                    *(float2*)(C32 + (size_t)(row + 8) * ldc + col) =
                        make_float2(acc[mi][ni][2], acc[mi][ni][3]);
                } else {
                    *(uint32_t*)(C16 + (size_t)row * ldc + col) =
                        packh2(acc[mi][ni][0], acc[mi][ni][1]);
                    *(uint32_t*)(C16 + (size_t)(row + 8) * ldc + col) =
                        packh2(acc[mi][ni][2], acc[mi][ni][3]);
                }
            }
        }
    }
}

// =====================================================================
// RoPE on fp16 q and ckv
// =====================================================================
__global__ void rope_kernel(__half* __restrict__ q, __half* __restrict__ ckv,
                            const int* __restrict__ position)
{
    int idx = blockIdx.x * blockDim.x + threadIdx.x;
    const int total = BS * 17 * 32;
    if (idx >= total) return;
    int j = idx & 31;
    int rest = idx >> 5;
    int h = rest % 17;
    int bs = rest / 17;
    int s = bs & (SEQ - 1);

    float pos = (float)position[s];
    float inv = __expf(-(float)(2 * j) * (9.210340371976184f / 64.0f));
    float ang = pos * inv;
    float sn, cs;
    sincosf(ang, &sn, &cs);

    __half* base = (h < 16)
        ? (q + (size_t)bs * QW + h * QH + NOPE)
        : (ckv + (size_t)bs * CKV_W + KVL);
    float t1 = __half2float(base[j]);
    float t2 = __half2float(base[j + 32]);
    base[j]      = __float2half_rn(t1 * cs - t2 * sn);
    base[j + 32] = __float2half_rn(t2 * cs + t1 * sn);
}

// =====================================================================
// Flash attention fp16 mma (reads q/kv/ckv fp16 directly, writes fp16)
// grid (SEQ/64, HEADS, BATCH), 128 threads.
// =====================================================================
#define KBUF 24576
#define VBUF 16384
#define ABUF (KBUF + VBUF)
#define ATTN_SMEM (2 * ABUF)

__device__ __forceinline__ uint32_t kaddr(uint32_t base, int row, int db) {
    uint32_t within = (uint32_t)(db & 127) ^ (uint32_t)((row & 7) << 4);
    return base + row * 384 + (uint32_t)(db & ~127) + within;
}
__device__ __forceinline__ uint32_t vaddr(uint32_t base, int row, int db) {
    uint32_t within = (uint32_t)(db & 127) ^ (uint32_t)((row & 7) << 4);
    return base + row * 256 + (uint32_t)(db & ~127) + within;
}

__global__ __launch_bounds__(128)
void attn_mma(const __half* __restrict__ q16, const __half* __restrict__ kv16,
              const __half* __restrict__ ckv16, __half* __restrict__ out)
{
    extern __shared__ char sm[];
    const uint32_t sb = smem_u32(sm);
    const int b = blockIdx.z, h = blockIdx.y, q0 = blockIdx.x * 64;
    const int tid = threadIdx.x, lane = tid & 31, w = tid >> 5;

    // ---- prologue: Q tile -> buf0 K area, extract fragments ----
    #pragma unroll
    for (int i = 0; i < 12; i++) {
        int idx = tid + i * 128;
        int row = idx / 24, c16 = idx % 24;
        const char* g = (const char*)(q16 +
            (size_t)(b * SEQ + q0 + row) * QW + h * QH) + c16 * 16;
        CPA(kaddr(sb, row, c16 * 16), g);
    }
    CPA_COMMIT();
    CPA_WAIT(0);
    __syncthreads();

    uint32_t qa[12][4];
    {
        int r = w * 16 + (lane & 15);
        int dhi = (lane >> 4) * 16;
        #pragma unroll
        for (int ks = 0; ks < 12; ks++)
            ldm_x4(kaddr(sb, r, ks * 32 + dhi), qa[ks]);
    }
    __syncthreads();

    // ---- K/V tile issuer: nope+v from kv16, rope from ckv16 ----
    auto issue = [&](int kt, int buf) {
        const uint32_t kb = sb + buf * ABUF;
        const uint32_t vb = kb + KBUF;
        const int key0 = kt * 64;
        #pragma unroll
        for (int i = 0; i < 12; i++) {
            int idx = tid + i * 128;
            int row = idx / 24, c16 = idx % 24;
            size_t trow = (size_t)(b * SEQ + key0 + row);
            const char* g = (c16 < 16)
                ? (const char*)(kv16 + trow * KVW + h * 256) + c16 * 16
                : (const char*)(ckv16 + trow * CKV_W + KVL) + (c16 - 16) * 16;
            CPA(kaddr(kb, row, c16 * 16), g);
        }
        #pragma unroll
        for (int i = 0; i < 8; i++) {
            int idx = tid + i * 128;
            int row = idx >> 4, c16 = idx & 15;
            const char* g = (const char*)(kv16 +
                (size_t)(b * SEQ + key0 + row) * KVW + h * 256 + 128) + c16 * 16;
            CPA(vaddr(vb, row, c16 * 16), g);
        }
        CPA_COMMIT();
    };

    float o[16][4];
    #pragma unroll
    for (int i = 0; i < 16; i++)
        #pragma unroll
        for (int j = 0; j < 4; j++) o[i][j] = 0.f;
    float m0 = -1e30f, m1 = -1e30f, l0 = 0.f, l1 = 0.f;
    const float sc = 0.07216878364870323f;  // 1/sqrt(192)

    issue(0, 0);

    for (int kt = 0; kt < SEQ / 64; kt++) {
        if (kt + 1 < SEQ / 64) {
            issue(kt + 1, (kt + 1) & 1);
            CPA_WAIT(1);
        } else {
            CPA_WAIT(0);
        }
        __syncthreads();

        const uint32_t kb = sb + (kt & 1) * ABUF;
        const uint32_t vb = kb + KBUF;

        // ---- S = Q K^T ----
        float s[8][4];
        #pragma unroll
        for (int i = 0; i < 8; i++)
            #pragma unroll
            for (int j = 0; j < 4; j++) s[i][j] = 0.f;

        const int krow_off = ((lane >> 4) << 3) + (lane & 7);
        const int kdim_off = ((lane >> 3) & 1) * 16;
        #pragma unroll
        for (int ks = 0; ks < 12; ks++) {
            #pragma unroll
            for (int kb4 = 0; kb4 < 4; kb4++) {
                uint32_t r[4];
                ldm_x4(kaddr(kb, kb4 * 16 + krow_off, ks * 32 + kdim_off), r);
                mma_f16(s[2 * kb4],     qa[ks], r[0], r[1]);
                mma_f16(s[2 * kb4 + 1], qa[ks], r[2], r[3]);
            }
        }

        // ---- online softmax ----
        float mx0 = -1e30f, mx1 = -1e30f;
        #pragma unroll
        for (int ni = 0; ni < 8; ni++) {
            mx0 = fmaxf(mx0, fmaxf(s[ni][0], s[ni][1]));
            mx1 = fmaxf(mx1, fmaxf(s[ni][2], s[ni][3]));
        }
        mx0 = fmaxf(mx0, __shfl_xor_sync(0xffffffffu, mx0, 1));
        mx0 = fmaxf(mx0, __shfl_xor_sync(0xffffffffu, mx0, 2));
        mx1 = fmaxf(mx1, __shfl_xor_sync(0xffffffffu, mx1, 1));
        mx1 = fmaxf(mx1, __shfl_xor_sync(0xffffffffu, mx1, 2));

        float mn0 = fmaxf(m0, mx0 * sc);
        float mn1 = fmaxf(m1, mx1 * sc);
        float a0 = __expf(m0 - mn0);
        float a1 = __expf(m1 - mn1);

        float rs0 = 0.f, rs1 = 0.f;
        uint32_t pa[4][4];
        #pragma unroll
        for (int ni = 0; ni < 8; ni++) {
            float p0 = __expf(s[ni][0] * sc - mn0);
            float p1 = __expf(s[ni][1] * sc - mn0);
            float p2 = __expf(s[ni][2] * sc - mn1);
            float p3 = __expf(s[ni][3] * sc - mn1);
            rs0 += p0 + p1;
            rs1 += p2 + p3;
            int kk = ni >> 1;
            if ((ni & 1) == 0) {
                pa[kk][0] = packh2(p0, p1);
                pa[kk][1] = packh2(p2, p3);
            } else {
                pa[kk][2] = packh2(p0, p1);
                pa[kk][3] = packh2(p2, p3);
            }
        }
        rs0 += __shfl_xor_sync(0xffffffffu, rs0, 1);
        rs0 += __shfl_xor_sync(0xffffffffu, rs0, 2);
        rs1 += __shfl_xor_sync(0xffffffffu, rs1, 1);
        rs1 += __shfl_xor_sync(0xffffffffu, rs1, 2);

        l0 = l0 * a0 + rs0;
        l1 = l1 * a1 + rs1;
        m0 = mn0; m1 = mn1;

        #pragma unroll
        for (int nj = 0; nj < 16; nj++) {
            o[nj][0] *= a0; o[nj][1] *= a0;
            o[nj][2] *= a1; o[nj][3] *= a1;
        }

        // ---- O += P V ----
        const int vrow_off = ((lane >> 3) & 1) * 8 + (lane & 7);
        const int vdim_off = (lane >> 4) * 16;
        #pragma unroll
        for (int kk = 0; kk < 4; kk++) {
            #pragma unroll
            for (int nb = 0; nb < 8; nb++) {
                uint32_t r[4];
                ldm_x4_t(vaddr(vb, kk * 16 + vrow_off, nb * 32 + vdim_off), r);
                mma_f16(o[2 * nb],     pa[kk], r[0], r[1]);
                mma_f16(o[2 * nb + 1], pa[kk], r[2], r[3]);
            }
        }
        __syncthreads();
    }

    // ---- normalize + fp16 store ----
    const float inv0 = 1.f / l0, inv1 = 1.f / l1;
    size_t rbase = (size_t)(b * SEQ + q0 + w * 16 + (lane >> 2)) * HID
                 + h * VH + (lane & 3) * 2;
    #pragma unroll
    for (int nj = 0; nj < 16; nj++) {
        *(uint32_t*)(out + rbase + nj * 8) =
            packh2(o[nj][0] * inv0, o[nj][1] * inv0);
        *(uint32_t*)(out + rbase + 8 * HID + nj * 8) =
            packh2(o[nj][2] * inv1, o[nj][3] * inv1);
    }
}

// =====================================================================
extern "C" void kernel_launch(void* const* d_in, const int* in_sizes, int n_in,
                              void* d_out, int out_size)
{
    const float* x        = (const float*)d_in[0];
    const int*   position = (const int*)  d_in[1];
    const float* Wq_down  = (const float*)d_in[2];
    const float* Wq_up    = (const float*)d_in[3];
    const float* Wkv_down = (const float*)d_in[4];
    const float* Wkv_up   = (const float*)d_in[5];
    const float* Wout     = (const float*)d_in[6];
    float*       out      = (float*)d_out;

    __half *x16, *cq, *qb, *ckv, *kvb, *attn, *w;
    cudaGetSymbolAddress((void**)&x16,  g_x16);
    cudaGetSymbolAddress((void**)&cq,   g_cq);
    cudaGetSymbolAddress((void**)&qb,   g_q);
    cudaGetSymbolAddress((void**)&ckv,  g_ckv);
    cudaGetSymbolAddress((void**)&kvb,  g_kv);
    cudaGetSymbolAddress((void**)&attn, g_attn);
    cudaGetSymbolAddress((void**)&w,    g_w);

    cudaFuncSetAttribute(gemm_f16, cudaFuncAttributeMaxDynamicSharedMemorySize,
                         GEMM_SMEM);
    cudaFuncSetAttribute(attn_mma, cudaFuncAttributeMaxDynamicSharedMemorySize,
                         ATTN_SMEM);

    // ---- conversions ----
    cvtx<<<BS * HID / 512, 256>>>(x, x16);
    wconv<<<dim3(1024/32, 2048/32), 256>>>(Wq_down,  w + O_WQD_HI, w + O_WQD_LO, 2048, 1024);
    wconv<<<dim3(3072/32, 1024/32), 256>>>(Wq_up,    w + O_WQU_HI, w + O_WQU_LO, 1024, 3072);
    wconv<<<dim3(576/32,  2048/32), 256>>>(Wkv_down, w + O_WKD_HI, w + O_WKD_LO, 2048, 576);
    wconv<<<dim3(4096/32, 512/32),  256>>>(Wkv_up,   w + O_WKU_HI, w + O_WKU_LO, 512,  4096);
    wconv<<<dim3(2048/32, 2048/32), 256>>>(Wout,     w + O_WO_HI,  w + O_WO_LO,  2048, 2048);

    // ---- GEMMs (fp16 2-pass) ----
    gemm_f16<<<dim3(QLORA/128, BS/128), 256, GEMM_SMEM>>>(
        x16, w + O_WQD_HI, w + O_WQD_LO, cq, nullptr, BS, QLORA, HID, HID, QLORA);
    gemm_f16<<<dim3(QW/128, BS/128), 256, GEMM_SMEM>>>(
        cq, w + O_WQU_HI, w + O_WQU_LO, qb, nullptr, BS, QW, QLORA, QLORA, QW);
    gemm_f16<<<dim3((CKV_W + 127)/128, BS/128), 256, GEMM_SMEM>>>(
        x16, w + O_WKD_HI, w + O_WKD_LO, ckv, nullptr, BS, CKV_W, HID, HID, CKV_W);

    rope_kernel<<<(BS*17*32 + 255)/256, 256>>>(qb, ckv, position);

    gemm_f16<<<dim3(KVW/128, BS/128), 256, GEMM_SMEM>>>(
        ckv, w + O_WKU_HI, w + O_WKU_LO, kvb, nullptr, BS, KVW, KVL, CKV_W, KVW);

    attn_mma<<<dim3(SEQ/64, HEADS, BATCH), 128, ATTN_SMEM>>>(qb, kvb, ckv, attn);

    gemm_f16<<<dim3(HID/128, BS/128), 256, GEMM_SMEM>>>(
        attn, w + O_WO_HI, w + O_WO_LO, nullptr, out, BS, HID, HID, HID, HID);
}

// round 6
// speedup vs baseline: 7.7232x; 1.4187x over previous
#include <cuda_runtime.h>
#include <cuda_fp16.h>
#include <math.h>
#include <stdint.h>

// ---------------- problem dims ----------------
#define HID     2048
#define HEADS   16
#define SEQ     2048
#define BATCH   2
#define BS      (BATCH*SEQ)          // 4096
#define QLORA   1024
#define QH      192
#define NOPE    128
#define ROPED   64
#define VH      128
#define KVL     512
#define CKV_W   576
#define QW      (HEADS*QH)           // 3072
#define KVW     (HEADS*(NOPE+VH))    // 4096

// ---------------- scratch (all fp16 intermediates) ----------------
__device__ __half g_x16 [(size_t)BS * HID];
__device__ __half g_cq  [(size_t)BS * QLORA];
__device__ __half g_q   [(size_t)BS * QW];
__device__ __half g_ckv [(size_t)BS * CKV_W];
__device__ __half g_kv  [(size_t)BS * KVW];
__device__ __half g_attn[(size_t)BS * HID];
// transposed fp16 weights (single precision pass)
#define WQD_SZ  (1024*2048)
#define WQU_SZ  (3072*1024)
#define WKD_SZ  (576*2048)
#define WKU_SZ  (4096*512)
#define WO_SZ   (2048*2048)
#define O_WQD 0
#define O_WQU (O_WQD + WQD_SZ)
#define O_WKD (O_WQU + WQU_SZ)
#define O_WKU (O_WKD + WKD_SZ)
#define O_WO  (O_WKU + WKU_SZ)
#define W_TOTAL (O_WO + WO_SZ)
__device__ __half g_w[W_TOTAL];

// ---------------- helpers ----------------
__device__ __forceinline__ uint32_t smem_u32(const void* p) {
    uint32_t a;
    asm("{ .reg .u64 t; cvta.to.shared.u64 t, %1; cvt.u32.u64 %0, t; }"
        : "=r"(a) : "l"(p));
    return a;
}
__device__ __forceinline__ void ldm_x4(uint32_t addr, uint32_t r[4]) {
    asm volatile("ldmatrix.sync.aligned.m8n8.x4.shared.b16 {%0,%1,%2,%3}, [%4];"
                 : "=r"(r[0]), "=r"(r[1]), "=r"(r[2]), "=r"(r[3]) : "r"(addr));
}
__device__ __forceinline__ void ldm_x4_t(uint32_t addr, uint32_t r[4]) {
    asm volatile("ldmatrix.sync.aligned.m8n8.x4.trans.shared.b16 {%0,%1,%2,%3}, [%4];"
                 : "=r"(r[0]), "=r"(r[1]), "=r"(r[2]), "=r"(r[3]) : "r"(addr));
}
__device__ __forceinline__ void mma_f16(float d[4], const uint32_t a[4],
                                        const uint32_t b0, const uint32_t b1) {
    asm volatile("mma.sync.aligned.m16n8k16.row.col.f32.f16.f16.f32 "
                 "{%0,%1,%2,%3}, {%4,%5,%6,%7}, {%8,%9}, {%0,%1,%2,%3};"
                 : "+f"(d[0]), "+f"(d[1]), "+f"(d[2]), "+f"(d[3])
                 : "r"(a[0]), "r"(a[1]), "r"(a[2]), "r"(a[3]), "r"(b0), "r"(b1));
}
__device__ __forceinline__ uint32_t packh2(float lo, float hi) {
    uint32_t d;
    asm("cvt.rn.f16x2.f32 %0, %1, %2;" : "=r"(d) : "f"(hi), "f"(lo));
    return d;
}
#define CPA(s, g) asm volatile("cp.async.cg.shared.global [%0], [%1], 16;" :: "r"(s), "l"(g))
#define CPA_COMMIT() asm volatile("cp.async.commit_group;")
#define CPA_WAIT(n)  asm volatile("cp.async.wait_group %0;" :: "n"(n))

// 128-byte-row swizzle: bank phase = row&7
__device__ __forceinline__ uint32_t sw128(uint32_t base, int row, int db) {
    return base + row * 128 + (uint32_t)(db ^ ((row & 7) << 4));
}

// =====================================================================
// x fp32 -> fp16
// =====================================================================
__global__ __launch_bounds__(256)
void cvtx(const float* __restrict__ x, __half* __restrict__ x16)
{
    int i = blockIdx.x * 256 + threadIdx.x;
    float2 v = ((const float2*)x)[i];
    ((__half2*)x16)[i] = __float22half2_rn(v);
}

// =====================================================================
// Weight transpose + fp16 convert: W[K,N] -> W16[N,K]
// =====================================================================
__global__ __launch_bounds__(256)
void wconv(const float* __restrict__ W, __half* __restrict__ hi, int K, int N)
{
    __shared__ float t[32][33];
    int n0 = blockIdx.x * 32, k0 = blockIdx.y * 32;
    int tx = threadIdx.x & 31, ty = threadIdx.x >> 5;
    #pragma unroll
    for (int j = 0; j < 4; j++)
        t[ty + 8*j][tx] = W[(size_t)(k0 + ty + 8*j) * N + n0 + tx];
    __syncthreads();
    #pragma unroll
    for (int j = 0; j < 4; j++)
        hi[(size_t)(n0 + ty + 8*j) * K + k0 + tx] = __float2half_rn(t[tx][ty + 8*j]);
}

// =====================================================================
// fp16 single-pass GEMM: C[M,N] = A[M,K] @ B[K,N]
// A fp16 row-major; B pre-transposed fp16 [N,K].
// CTA 128x128, BK=64, 8 warps (2x4), warp tile 64x32.
// 3-stage cp.async pipeline: per stage A 16K | B 16K = 32KB.
// =====================================================================
#define GBUF 32768
#define GEMM_SMEM (3*GBUF)

__global__ __launch_bounds__(256, 2)
void gemm_f16(const __half* __restrict__ A,
              const __half* __restrict__ B,
              __half* __restrict__ C16, float* __restrict__ C32,
              int M, int N, int K, int lda, int ldc)
{
    extern __shared__ char sm[];
    const uint32_t sb = smem_u32(sm);
    const int tid  = threadIdx.x;
    const int lane = tid & 31;
    const int wid  = tid >> 5;
    const int wm   = (wid >> 2) * 64;
    const int wn   = (wid & 3) * 32;
    const int m0   = blockIdx.y * 128;
    const int n0   = blockIdx.x * 128;

    float acc[4][4][4];
    #pragma unroll
    for (int i = 0; i < 4; i++)
        #pragma unroll
        for (int j = 0; j < 4; j++)
            #pragma unroll
            for (int c = 0; c < 4; c++) acc[i][j][c] = 0.f;

    const int T = K >> 6;
    const int arow = tid >> 1, ac = (tid & 1) * 4;   // 2 threads/row, 4x16B each

    auto issue = [&](int t) {
        const uint32_t bb = sb + (t % 3) * GBUF;
        const int k0 = t << 6;
        const char* ga = (const char*)(A + (size_t)(m0 + arow) * lda + k0) + ac * 16;
        #pragma unroll
        for (int c = 0; c < 4; c++)
            CPA(sw128(bb, arow, (ac + c) * 16), ga + c * 16);
        int n = n0 + arow;
        if (n >= N) n = N - 1;
        const char* gb = (const char*)(B + (size_t)n * K + k0) + ac * 16;
        #pragma unroll
        for (int c = 0; c < 4; c++)
            CPA(sw128(bb + 16384, arow, (ac + c) * 16), gb + c * 16);
        CPA_COMMIT();
    };

    issue(0);
    if (T > 1) issue(1);
    if (T > 2) issue(2);

    for (int t = 0; t < T; t++) {
        if (t + 2 < T)      CPA_WAIT(2);
        else if (t + 1 < T) CPA_WAIT(1);
        else                CPA_WAIT(0);
        __syncthreads();

        const uint32_t bb = sb + (t % 3) * GBUF;
        const int klo = (lane >> 4) << 4;

        #pragma unroll
        for (int ks = 0; ks < 4; ks++) {
            uint32_t af[4][4];
            #pragma unroll
            for (int mi = 0; mi < 4; mi++)
                ldm_x4(sw128(bb, wm + mi * 16 + (lane & 15), ks * 32 + klo), af[mi]);
            uint32_t bf[4][2];
            #pragma unroll
            for (int np = 0; np < 2; np++) {
                uint32_t q[4];
                ldm_x4(sw128(bb + 16384, wn + np * 16 + (lane & 15), ks * 32 + klo), q);
                bf[2*np][0] = q[0]; bf[2*np][1] = q[2];
                bf[2*np+1][0] = q[1]; bf[2*np+1][1] = q[3];
            }
            #pragma unroll
            for (int mi = 0; mi < 4; mi++)
                #pragma unroll
                for (int ni = 0; ni < 4; ni++)
                    mma_f16(acc[mi][ni], af[mi], bf[ni][0], bf[ni][1]);
        }
        __syncthreads();
        if (t + 3 < T) issue(t + 3);
    }

    // ---- epilogue ----
    const int r0 = lane >> 2, c0 = (lane & 3) * 2;
    #pragma unroll
    for (int mi = 0; mi < 4; mi++) {
        #pragma unroll
        for (int ni = 0; ni < 4; ni++) {
            int row = m0 + wm + mi * 16 + r0;
            int col = n0 + wn + ni * 8 + c0;
            if (col < N) {
                if (C32) {
                    *(float2*)(C32 + (size_t)row * ldc + col) =
                        make_float2(acc[mi][ni][0], acc[mi][ni][1]);
                    *(float2*)(C32 + (size_t)(row + 8) * ldc + col) =
                        make_float2(acc[mi][ni][2], acc[mi][ni][3]);
                } else {
                    *(uint32_t*)(C16 + (size_t)row * ldc + col) =
                        packh2(acc[mi][ni][0], acc[mi][ni][1]);
                    *(uint32_t*)(C16 + (size_t)(row + 8) * ldc + col) =
                        packh2(acc[mi][ni][2], acc[mi][ni][3]);
                }
            }
        }
    }
}

// =====================================================================
// RoPE on fp16 q and ckv
// =====================================================================
__global__ void rope_kernel(__half* __restrict__ q, __half* __restrict__ ckv,
                            const int* __restrict__ position)
{
    int idx = blockIdx.x * blockDim.x + threadIdx.x;
    const int total = BS * 17 * 32;
    if (idx >= total) return;
    int j = idx & 31;
    int rest = idx >> 5;
    int h = rest % 17;
    int bs = rest / 17;
    int s = bs & (SEQ - 1);

    float pos = (float)position[s];
    float inv = __expf(-(float)(2 * j) * (9.210340371976184f / 64.0f));
    float ang = pos * inv;
    float sn, cs;
    sincosf(ang, &sn, &cs);

    __half* base = (h < 16)
        ? (q + (size_t)bs * QW + h * QH + NOPE)
        : (ckv + (size_t)bs * CKV_W + KVL);
    float t1 = __half2float(base[j]);
    float t2 = __half2float(base[j + 32]);
    base[j]      = __float2half_rn(t1 * cs - t2 * sn);
    base[j + 32] = __float2half_rn(t2 * cs + t1 * sn);
}

// =====================================================================
// Flash attention fp16 mma (unchanged from R5)
// =====================================================================
#define KBUF 24576
#define VBUF 16384
#define ABUF (KBUF + VBUF)
#define ATTN_SMEM (2 * ABUF)

__device__ __forceinline__ uint32_t kaddr(uint32_t base, int row, int db) {
    uint32_t within = (uint32_t)(db & 127) ^ (uint32_t)((row & 7) << 4);
    return base + row * 384 + (uint32_t)(db & ~127) + within;
}
__device__ __forceinline__ uint32_t vaddr(uint32_t base, int row, int db) {
    uint32_t within = (uint32_t)(db & 127) ^ (uint32_t)((row & 7) << 4);
    return base + row * 256 + (uint32_t)(db & ~127) + within;
}

__global__ __launch_bounds__(128)
void attn_mma(const __half* __restrict__ q16, const __half* __restrict__ kv16,
              const __half* __restrict__ ckv16, __half* __restrict__ out)
{
    extern __shared__ char sm[];
    const uint32_t sb = smem_u32(sm);
    const int b = blockIdx.z, h = blockIdx.y, q0 = blockIdx.x * 64;
    const int tid = threadIdx.x, lane = tid & 31, w = tid >> 5;

    // ---- prologue: Q tile -> buf0 K area, extract fragments ----
    #pragma unroll
    for (int i = 0; i < 12; i++) {
        int idx = tid + i * 128;
        int row = idx / 24, c16 = idx % 24;
        const char* g = (const char*)(q16 +
            (size_t)(b * SEQ + q0 + row) * QW + h * QH) + c16 * 16;
        CPA(kaddr(sb, row, c16 * 16), g);
    }
    CPA_COMMIT();
    CPA_WAIT(0);
    __syncthreads();

    uint32_t qa[12][4];
    {
        int r = w * 16 + (lane & 15);
        int dhi = (lane >> 4) * 16;
        #pragma unroll
        for (int ks = 0; ks < 12; ks++)
            ldm_x4(kaddr(sb, r, ks * 32 + dhi), qa[ks]);
    }
    __syncthreads();

    auto issue = [&](int kt, int buf) {
        const uint32_t kb = sb + buf * ABUF;
        const uint32_t vb = kb + KBUF;
        const int key0 = kt * 64;
        #pragma unroll
        for (int i = 0; i < 12; i++) {
            int idx = tid + i * 128;
            int row = idx / 24, c16 = idx % 24;
            size_t trow = (size_t)(b * SEQ + key0 + row);
            const char* g = (c16 < 16)
                ? (const char*)(kv16 + trow * KVW + h * 256) + c16 * 16
                : (const char*)(ckv16 + trow * CKV_W + KVL) + (c16 - 16) * 16;
            CPA(kaddr(kb, row, c16 * 16), g);
        }
        #pragma unroll
        for (int i = 0; i < 8; i++) {
            int idx = tid + i * 128;
            int row = idx >> 4, c16 = idx & 15;
            const char* g = (const char*)(kv16 +
                (size_t)(b * SEQ + key0 + row) * KVW + h * 256 + 128) + c16 * 16;
            CPA(vaddr(vb, row, c16 * 16), g);
        }
        CPA_COMMIT();
    };

    float o[16][4];
    #pragma unroll
    for (int i = 0; i < 16; i++)
        #pragma unroll
        for (int j = 0; j < 4; j++) o[i][j] = 0.f;
    float m0 = -1e30f, m1 = -1e30f, l0 = 0.f, l1 = 0.f;
    const float sc = 0.07216878364870323f;  // 1/sqrt(192)

    issue(0, 0);

    for (int kt = 0; kt < SEQ / 64; kt++) {
        if (kt + 1 < SEQ / 64) {
            issue(kt + 1, (kt + 1) & 1);
            CPA_WAIT(1);
        } else {
            CPA_WAIT(0);
        }
        __syncthreads();

        const uint32_t kb = sb + (kt & 1) * ABUF;
        const uint32_t vb = kb + KBUF;

        float s[8][4];
        #pragma unroll
        for (int i = 0; i < 8; i++)
            #pragma unroll
            for (int j = 0; j < 4; j++) s[i][j] = 0.f;

        const int krow_off = ((lane >> 4) << 3) + (lane & 7);
        const int kdim_off = ((lane >> 3) & 1) * 16;
        #pragma unroll
        for (int ks = 0; ks < 12; ks++) {
            #pragma unroll
            for (int kb4 = 0; kb4 < 4; kb4++) {
                uint32_t r[4];
                ldm_x4(kaddr(kb, kb4 * 16 + krow_off, ks * 32 + kdim_off), r);
                mma_f16(s[2 * kb4],     qa[ks], r[0], r[1]);
                mma_f16(s[2 * kb4 + 1], qa[ks], r[2], r[3]);
            }
        }

        float mx0 = -1e30f, mx1 = -1e30f;
        #pragma unroll
        for (int ni = 0; ni < 8; ni++) {
            mx0 = fmaxf(mx0, fmaxf(s[ni][0], s[ni][1]));
            mx1 = fmaxf(mx1, fmaxf(s[ni][2], s[ni][3]));
        }
        mx0 = fmaxf(mx0, __shfl_xor_sync(0xffffffffu, mx0, 1));
        mx0 = fmaxf(mx0, __shfl_xor_sync(0xffffffffu, mx0, 2));
        mx1 = fmaxf(mx1, __shfl_xor_sync(0xffffffffu, mx1, 1));
        mx1 = fmaxf(mx1, __shfl_xor_sync(0xffffffffu, mx1, 2));

        float mn0 = fmaxf(m0, mx0 * sc);
        float mn1 = fmaxf(m1, mx1 * sc);
        float a0 = __expf(m0 - mn0);
        float a1 = __expf(m1 - mn1);

        float rs0 = 0.f, rs1 = 0.f;
        uint32_t pa[4][4];
        #pragma unroll
        for (int ni = 0; ni < 8; ni++) {
            float p0 = __expf(s[ni][0] * sc - mn0);
            float p1 = __expf(s[ni][1] * sc - mn0);
            float p2 = __expf(s[ni][2] * sc - mn1);
            float p3 = __expf(s[ni][3] * sc - mn1);
            rs0 += p0 + p1;
            rs1 += p2 + p3;
            int kk = ni >> 1;
            if ((ni & 1) == 0) {
                pa[kk][0] = packh2(p0, p1);
                pa[kk][1] = packh2(p2, p3);
            } else {
                pa[kk][2] = packh2(p0, p1);
                pa[kk][3] = packh2(p2, p3);
            }
        }
        rs0 += __shfl_xor_sync(0xffffffffu, rs0, 1);
        rs0 += __shfl_xor_sync(0xffffffffu, rs0, 2);
        rs1 += __shfl_xor_sync(0xffffffffu, rs1, 1);
        rs1 += __shfl_xor_sync(0xffffffffu, rs1, 2);

        l0 = l0 * a0 + rs0;
        l1 = l1 * a1 + rs1;
        m0 = mn0; m1 = mn1;

        #pragma unroll
        for (int nj = 0; nj < 16; nj++) {
            o[nj][0] *= a0; o[nj][1] *= a0;
            o[nj][2] *= a1; o[nj][3] *= a1;
        }

        const int vrow_off = ((lane >> 3) & 1) * 8 + (lane & 7);
        const int vdim_off = (lane >> 4) * 16;
        #pragma unroll
        for (int kk = 0; kk < 4; kk++) {
            #pragma unroll
            for (int nb = 0; nb < 8; nb++) {
                uint32_t r[4];
                ldm_x4_t(vaddr(vb, kk * 16 + vrow_off, nb * 32 + vdim_off), r);
                mma_f16(o[2 * nb],     pa[kk], r[0], r[1]);
                mma_f16(o[2 * nb + 1], pa[kk], r[2], r[3]);
            }
        }
        __syncthreads();
    }

    const float inv0 = 1.f / l0, inv1 = 1.f / l1;
    size_t rbase = (size_t)(b * SEQ + q0 + w * 16 + (lane >> 2)) * HID
                 + h * VH + (lane & 3) * 2;
    #pragma unroll
    for (int nj = 0; nj < 16; nj++) {
        *(uint32_t*)(out + rbase + nj * 8) =
            packh2(o[nj][0] * inv0, o[nj][1] * inv0);
        *(uint32_t*)(out + rbase + 8 * HID + nj * 8) =
            packh2(o[nj][2] * inv1, o[nj][3] * inv1);
    }
}

// =====================================================================
extern "C" void kernel_launch(void* const* d_in, const int* in_sizes, int n_in,
                              void* d_out, int out_size)
{
    const float* x        = (const float*)d_in[0];
    const int*   position = (const int*)  d_in[1];
    const float* Wq_down  = (const float*)d_in[2];
    const float* Wq_up    = (const float*)d_in[3];
    const float* Wkv_down = (const float*)d_in[4];
    const float* Wkv_up   = (const float*)d_in[5];
    const float* Wout     = (const float*)d_in[6];
    float*       out      = (float*)d_out;

    __half *x16, *cq, *qb, *ckv, *kvb, *attn, *w;
    cudaGetSymbolAddress((void**)&x16,  g_x16);
    cudaGetSymbolAddress((void**)&cq,   g_cq);
    cudaGetSymbolAddress((void**)&qb,   g_q);
    cudaGetSymbolAddress((void**)&ckv,  g_ckv);
    cudaGetSymbolAddress((void**)&kvb,  g_kv);
    cudaGetSymbolAddress((void**)&attn, g_attn);
    cudaGetSymbolAddress((void**)&w,    g_w);

    cudaFuncSetAttribute(gemm_f16, cudaFuncAttributeMaxDynamicSharedMemorySize,
                         GEMM_SMEM);
    cudaFuncSetAttribute(attn_mma, cudaFuncAttributeMaxDynamicSharedMemorySize,
                         ATTN_SMEM);

    // ---- conversions ----
    cvtx<<<BS * HID / 512, 256>>>(x, x16);
    wconv<<<dim3(1024/32, 2048/32), 256>>>(Wq_down,  w + O_WQD, 2048, 1024);
    wconv<<<dim3(3072/32, 1024/32), 256>>>(Wq_up,    w + O_WQU, 1024, 3072);
    wconv<<<dim3(576/32,  2048/32), 256>>>(Wkv_down, w + O_WKD, 2048, 576);
    wconv<<<dim3(4096/32, 512/32),  256>>>(Wkv_up,   w + O_WKU, 512,  4096);
    wconv<<<dim3(2048/32, 2048/32), 256>>>(Wout,     w + O_WO,  2048, 2048);

    // ---- GEMMs (fp16 single-pass) ----
    gemm_f16<<<dim3(QLORA/128, BS/128), 256, GEMM_SMEM>>>(
        x16, w + O_WQD, cq, nullptr, BS, QLORA, HID, HID, QLORA);
    gemm_f16<<<dim3(QW/128, BS/128), 256, GEMM_SMEM>>>(
        cq, w + O_WQU, qb, nullptr, BS, QW, QLORA, QLORA, QW);
    gemm_f16<<<dim3((CKV_W + 127)/128, BS/128), 256, GEMM_SMEM>>>(
        x16, w + O_WKD, ckv, nullptr, BS, CKV_W, HID, HID, CKV_W);

    rope_kernel<<<(BS*17*32 + 255)/256, 256>>>(qb, ckv, position);

    gemm_f16<<<dim3(KVW/128, BS/128), 256, GEMM_SMEM>>>(
        ckv, w + O_WKU, kvb, nullptr, BS, KVW, KVL, CKV_W, KVW);

    attn_mma<<<dim3(SEQ/64, HEADS, BATCH), 128, ATTN_SMEM>>>(qb, kvb, ckv, attn);

    gemm_f16<<<dim3(HID/128, BS/128), 256, GEMM_SMEM>>>(
        attn, w + O_WO, nullptr, out, BS, HID, HID, HID, HID);
}

// round 8
// speedup vs baseline: 8.3420x; 1.0801x over previous
#include <cuda_runtime.h>
#include <cuda_fp16.h>
#include <math.h>
#include <stdint.h>

// ---------------- problem dims ----------------
#define HID     2048
#define HEADS   16
#define SEQ     2048
#define BATCH   2
#define BS      (BATCH*SEQ)          // 4096
#define QLORA   1024
#define QH      192
#define NOPE    128
#define ROPED   64
#define VH      128
#define KVL     512
#define CKV_W   576
#define CQK_W   1600                 // QLORA + CKV_W (merged down-proj output)
#define QW      (HEADS*QH)           // 3072
#define KVW     (HEADS*(NOPE+VH))    // 4096

// ---------------- scratch (all fp16 intermediates) ----------------
__device__ __half g_x16 [(size_t)BS * HID];
__device__ __half g_cqk [(size_t)BS * CQK_W];   // [:,0:1024]=cq, [:,1024:1600]=ckv
__device__ __half g_q   [(size_t)BS * QW];
__device__ __half g_kv  [(size_t)BS * KVW];
__device__ __half g_attn[(size_t)BS * HID];
// transposed fp16 weights
#define WDN_SZ  (1600*2048)   // merged Wq_down|Wkv_down, [1600,2048]
#define WQU_SZ  (3072*1024)
#define WKU_SZ  (4096*512)
#define WO_SZ   (2048*2048)
#define O_WDN 0
#define O_WQU (O_WDN + WDN_SZ)
#define O_WKU (O_WQU + WQU_SZ)
#define O_WO  (O_WKU + WKU_SZ)
#define W_TOTAL (O_WO + WO_SZ)
__device__ __half g_w[W_TOTAL];

// ---------------- helpers ----------------
__device__ __forceinline__ uint32_t smem_u32(const void* p) {
    uint32_t a;
    asm("{ .reg .u64 t; cvta.to.shared.u64 t, %1; cvt.u32.u64 %0, t; }"
        : "=r"(a) : "l"(p));
    return a;
}
__device__ __forceinline__ void ldm_x4(uint32_t addr, uint32_t r[4]) {
    asm volatile("ldmatrix.sync.aligned.m8n8.x4.shared.b16 {%0,%1,%2,%3}, [%4];"
                 : "=r"(r[0]), "=r"(r[1]), "=r"(r[2]), "=r"(r[3]) : "r"(addr));
}
__device__ __forceinline__ void ldm_x4_t(uint32_t addr, uint32_t r[4]) {
    asm volatile("ldmatrix.sync.aligned.m8n8.x4.trans.shared.b16 {%0,%1,%2,%3}, [%4];"
                 : "=r"(r[0]), "=r"(r[1]), "=r"(r[2]), "=r"(r[3]) : "r"(addr));
}
__device__ __forceinline__ void mma_f16(float d[4], const uint32_t a[4],
                                        const uint32_t b0, const uint32_t b1) {
    asm volatile("mma.sync.aligned.m16n8k16.row.col.f32.f16.f16.f32 "
                 "{%0,%1,%2,%3}, {%4,%5,%6,%7}, {%8,%9}, {%0,%1,%2,%3};"
                 : "+f"(d[0]), "+f"(d[1]), "+f"(d[2]), "+f"(d[3])
                 : "r"(a[0]), "r"(a[1]), "r"(a[2]), "r"(a[3]), "r"(b0), "r"(b1));
}
__device__ __forceinline__ uint32_t packh2(float lo, float hi) {
    uint32_t d;
    asm("cvt.rn.f16x2.f32 %0, %1, %2;" : "=r"(d) : "f"(hi), "f"(lo));
    return d;
}
#define CPA(s, g) asm volatile("cp.async.cg.shared.global [%0], [%1], 16;" :: "r"(s), "l"(g))
#define CPA_COMMIT() asm volatile("cp.async.commit_group;")
#define CPA_WAIT(n)  asm volatile("cp.async.wait_group %0;" :: "n"(n))

__device__ __forceinline__ uint32_t sw128(uint32_t base, int row, int db) {
    return base + row * 128 + (uint32_t)(db ^ ((row & 7) << 4));
}

// =====================================================================
// prep: fused x->fp16 conversion + all 5 weight transposes (one launch)
// block dispatch: [0,16384) cvtx | then wconv tiles
// =====================================================================
#define CVT_BLKS   16384
#define WDNQ_BLKS  2048   // Wq_down  [2048,1024]: 32 x-tiles * 64 y
#define WDNK_BLKS  1152   // Wkv_down [2048,576]:  18 * 64
#define WQU_BLKS   3072   // Wq_up    [1024,3072]: 96 * 32
#define WKU_BLKS   2048   // Wkv_up   [512,4096]: 128 * 16
#define WO_BLKS    4096   // Wout     [2048,2048]: 64 * 64
#define PREP_BLKS  (CVT_BLKS + WDNQ_BLKS + WDNK_BLKS + WQU_BLKS + WKU_BLKS + WO_BLKS)

__global__ __launch_bounds__(256)
void prep(const float* __restrict__ x,
          const float* __restrict__ Wq_down, const float* __restrict__ Wkv_down,
          const float* __restrict__ Wq_up,   const float* __restrict__ Wkv_up,
          const float* __restrict__ Wout,
          __half* __restrict__ x16, __half* __restrict__ w)
{
    __shared__ float t[32][33];
    const int bid = blockIdx.x;
    if (bid < CVT_BLKS) {
        int i = bid * 256 + threadIdx.x;
        float2 v = ((const float2*)x)[i];
        ((__half2*)x16)[i] = __float22half2_rn(v);
        return;
    }
    int tb = bid - CVT_BLKS;
    const float* W;
    __half* dst;
    int K, N, nt;
    if (tb < WDNQ_BLKS) {
        W = Wq_down; dst = w + O_WDN; K = 2048; N = 1024; nt = 32;
    } else if ((tb -= WDNQ_BLKS) < WDNK_BLKS) {
        W = Wkv_down; dst = w + O_WDN + (size_t)1024 * 2048; K = 2048; N = 576; nt = 18;
    } else if ((tb -= WDNK_BLKS) < WQU_BLKS) {
        W = Wq_up; dst = w + O_WQU; K = 1024; N = 3072; nt = 96;
    } else if ((tb -= WQU_BLKS) < WKU_BLKS) {
        W = Wkv_up; dst = w + O_WKU; K = 512; N = 4096; nt = 128;
    } else {
        tb -= WKU_BLKS;
        W = Wout; dst = w + O_WO; K = 2048; N = 2048; nt = 64;
    }
    const int n0 = (tb % nt) * 32, k0 = (tb / nt) * 32;
    const int tx = threadIdx.x & 31, ty = threadIdx.x >> 5;
    #pragma unroll
    for (int j = 0; j < 4; j++)
        t[ty + 8*j][tx] = W[(size_t)(k0 + ty + 8*j) * N + n0 + tx];
    __syncthreads();
    #pragma unroll
    for (int j = 0; j < 4; j++)
        dst[(size_t)(n0 + ty + 8*j) * K + k0 + tx] = __float2half_rn(t[tx][ty + 8*j]);
}

// =====================================================================
// fp16 single-pass GEMM body (R6 mainloop, block coords as params)
// =====================================================================
#define GBUF 32768
#define GEMM_SMEM (3*GBUF)

__device__ __forceinline__
void gemm_body(const __half* __restrict__ A, const __half* __restrict__ B,
               __half* __restrict__ C16, float* __restrict__ C32,
               int M, int N, int K, int lda, int ldc, int bx, int by)
{
    extern __shared__ char sm[];
    const uint32_t sb = smem_u32(sm);
    const int tid  = threadIdx.x;
    const int lane = tid & 31;
    const int wid  = tid >> 5;
    const int wm   = (wid >> 2) * 64;
    const int wn   = (wid & 3) * 32;
    const int m0   = by * 128;
    const int n0   = bx * 128;

    float acc[4][4][4];
    #pragma unroll
    for (int i = 0; i < 4; i++)
        #pragma unroll
        for (int j = 0; j < 4; j++)
            #pragma unroll
            for (int c = 0; c < 4; c++) acc[i][j][c] = 0.f;

    const int T = K >> 6;
    const int arow = tid >> 1, ac = (tid & 1) * 4;

    auto issue = [&](int t) {
        const uint32_t bb = sb + (t % 3) * GBUF;
        const int k0 = t << 6;
        const char* ga = (const char*)(A + (size_t)(m0 + arow) * lda + k0) + ac * 16;
        #pragma unroll
        for (int c = 0; c < 4; c++)
            CPA(sw128(bb, arow, (ac + c) * 16), ga + c * 16);
        int n = n0 + arow;
        if (n >= N) n = N - 1;
        const char* gb = (const char*)(B + (size_t)n * K + k0) + ac * 16;
        #pragma unroll
        for (int c = 0; c < 4; c++)
            CPA(sw128(bb + 16384, arow, (ac + c) * 16), gb + c * 16);
        CPA_COMMIT();
    };

    issue(0);
    if (T > 1) issue(1);
    if (T > 2) issue(2);

    for (int t = 0; t < T; t++) {
        if (t + 2 < T)      CPA_WAIT(2);
        else if (t + 1 < T) CPA_WAIT(1);
        else                CPA_WAIT(0);
        __syncthreads();

        const uint32_t bb = sb + (t % 3) * GBUF;
        const int klo = (lane >> 4) << 4;

        #pragma unroll
        for (int ks = 0; ks < 4; ks++) {
            uint32_t af[4][4];
            #pragma unroll
            for (int mi = 0; mi < 4; mi++)
                ldm_x4(sw128(bb, wm + mi * 16 + (lane & 15), ks * 32 + klo), af[mi]);
            uint32_t bf[4][2];
            #pragma unroll
            for (int np = 0; np < 2; np++) {
                uint32_t q[4];
                ldm_x4(sw128(bb + 16384, wn + np * 16 + (lane & 15), ks * 32 + klo), q);
                bf[2*np][0] = q[0]; bf[2*np][1] = q[2];
                bf[2*np+1][0] = q[1]; bf[2*np+1][1] = q[3];
            }
            #pragma unroll
            for (int mi = 0; mi < 4; mi++)
                #pragma unroll
                for (int ni = 0; ni < 4; ni++)
                    mma_f16(acc[mi][ni], af[mi], bf[ni][0], bf[ni][1]);
        }
        __syncthreads();
        if (t + 3 < T) issue(t + 3);
    }

    const int r0 = lane >> 2, c0 = (lane & 3) * 2;
    #pragma unroll
    for (int mi = 0; mi < 4; mi++) {
        #pragma unroll
        for (int ni = 0; ni < 4; ni++) {
            int row = m0 + wm + mi * 16 + r0;
            int col = n0 + wn + ni * 8 + c0;
            if (col < N) {
                if (C32) {
                    *(float2*)(C32 + (size_t)row * ldc + col) =
                        make_float2(acc[mi][ni][0], acc[mi][ni][1]);
                    *(float2*)(C32 + (size_t)(row + 8) * ldc + col) =
                        make_float2(acc[mi][ni][2], acc[mi][ni][3]);
                } else {
                    *(uint32_t*)(C16 + (size_t)row * ldc + col) =
                        packh2(acc[mi][ni][0], acc[mi][ni][1]);
                    *(uint32_t*)(C16 + (size_t)(row + 8) * ldc + col) =
                        packh2(acc[mi][ni][2], acc[mi][ni][3]);
                }
            }
        }
    }
}

__global__ __launch_bounds__(256, 2)
void gemm_f16(const __half* __restrict__ A, const __half* __restrict__ B,
              __half* __restrict__ C16, float* __restrict__ C32,
              int M, int N, int K, int lda, int ldc)
{
    gemm_body(A, B, C16, C32, M, N, K, lda, ldc, blockIdx.x, blockIdx.y);
}

// fused q-up (24 x-tiles) + kv-up (32 x-tiles); grid (56, 32)
__global__ __launch_bounds__(256, 2)
void gemm_up(const __half* __restrict__ cqk,
             const __half* __restrict__ wqu, const __half* __restrict__ wku,
             __half* __restrict__ qb, __half* __restrict__ kvb)
{
    if (blockIdx.x < QW / 128)
        gemm_body(cqk, wqu, qb, nullptr, BS, QW, QLORA, CQK_W, QW,
                  blockIdx.x, blockIdx.y);
    else
        gemm_body(cqk + 1024, wku, kvb, nullptr, BS, KVW, KVL, CQK_W, KVW,
                  blockIdx.x - QW / 128, blockIdx.y);
}

// =====================================================================
// RoPE on fp16 q and ckv (ckv lives in cqk at column 1024)
// =====================================================================
__global__ void rope_kernel(__half* __restrict__ q, __half* __restrict__ cqk,
                            const int* __restrict__ position)
{
    int idx = blockIdx.x * blockDim.x + threadIdx.x;
    const int total = BS * 17 * 32;
    if (idx >= total) return;
    int j = idx & 31;
    int rest = idx >> 5;
    int h = rest % 17;
    int bs = rest / 17;
    int s = bs & (SEQ - 1);

    float pos = (float)position[s];
    float inv = __expf(-(float)(2 * j) * (9.210340371976184f / 64.0f));
    float ang = pos * inv;
    float sn, cs;
    sincosf(ang, &sn, &cs);

    __half* base = (h < 16)
        ? (q + (size_t)bs * QW + h * QH + NOPE)
        : (cqk + (size_t)bs * CQK_W + 1024 + KVL);
    float t1 = __half2float(base[j]);
    float t2 = __half2float(base[j + 32]);
    base[j]      = __float2half_rn(t1 * cs - t2 * sn);
    base[j + 32] = __float2half_rn(t2 * cs + t1 * sn);
}

// =====================================================================
// Flash attention fp16 mma (unchanged from R7)
// =====================================================================
#define KBUF 24576
#define VBUF 16384
#define ABUF (KBUF + VBUF)
#define ATTN_SMEM (2 * ABUF)

__device__ __forceinline__ uint32_t kaddr(uint32_t base, int row, int db) {
    uint32_t within = (uint32_t)(db & 127) ^ (uint32_t)((row & 7) << 4);
    return base + row * 384 + (uint32_t)(db & ~127) + within;
}
__device__ __forceinline__ uint32_t vaddr(uint32_t base, int row, int db) {
    uint32_t within = (uint32_t)(db & 127) ^ (uint32_t)((row & 7) << 4);
    return base + row * 256 + (uint32_t)(db & ~127) + within;
}

__global__ __launch_bounds__(128)
void attn_mma(const __half* __restrict__ q16, const __half* __restrict__ kv16,
              const __half* __restrict__ cqk, __half* __restrict__ out)
{
    extern __shared__ char sm[];
    const uint32_t sb = smem_u32(sm);
    const int b = blockIdx.z, h = blockIdx.y, q0 = blockIdx.x * 64;
    const int tid = threadIdx.x, lane = tid & 31, w = tid >> 5;

    #pragma unroll
    for (int i = 0; i < 12; i++) {
        int idx = tid + i * 128;
        int row = idx / 24, c16 = idx % 24;
        const char* g = (const char*)(q16 +
            (size_t)(b * SEQ + q0 + row) * QW + h * QH) + c16 * 16;
        CPA(kaddr(sb, row, c16 * 16), g);
    }
    CPA_COMMIT();
    CPA_WAIT(0);
    __syncthreads();

    uint32_t qa[12][4];
    {
        int r = w * 16 + (lane & 15);
        int dhi = (lane >> 4) * 16;
        #pragma unroll
        for (int ks = 0; ks < 12; ks++)
            ldm_x4(kaddr(sb, r, ks * 32 + dhi), qa[ks]);
    }
    __syncthreads();

    auto issue = [&](int kt, int buf) {
        const uint32_t kb = sb + buf * ABUF;
        const uint32_t vb = kb + KBUF;
        const int key0 = kt * 64;
        #pragma unroll
        for (int i = 0; i < 12; i++) {
            int idx = tid + i * 128;
            int row = idx / 24, c16 = idx % 24;
            size_t trow = (size_t)(b * SEQ + key0 + row);
            const char* g = (c16 < 16)
                ? (const char*)(kv16 + trow * KVW + h * 256) + c16 * 16
                : (const char*)(cqk + trow * CQK_W + 1536) + (c16 - 16) * 16;
            CPA(kaddr(kb, row, c16 * 16), g);
        }
        #pragma unroll
        for (int i = 0; i < 8; i++) {
            int idx = tid + i * 128;
            int row = idx >> 4, c16 = idx & 15;
            const char* g = (const char*)(kv16 +
                (size_t)(b * SEQ + key0 + row) * KVW + h * 256 + 128) + c16 * 16;
            CPA(vaddr(vb, row, c16 * 16), g);
        }
        CPA_COMMIT();
    };

    float o[16][4];
    #pragma unroll
    for (int i = 0; i < 16; i++)
        #pragma unroll
        for (int j = 0; j < 4; j++) o[i][j] = 0.f;
    float m0 = -1e30f, m1 = -1e30f, l0 = 0.f, l1 = 0.f;
    const float sc = 0.07216878364870323f;

    issue(0, 0);

    for (int kt = 0; kt < SEQ / 64; kt++) {
        if (kt + 1 < SEQ / 64) {
            issue(kt + 1, (kt + 1) & 1);
            CPA_WAIT(1);
        } else {
            CPA_WAIT(0);
        }
        __syncthreads();

        const uint32_t kb = sb + (kt & 1) * ABUF;
        const uint32_t vb = kb + KBUF;

        float s[8][4];
        #pragma unroll
        for (int i = 0; i < 8; i++)
            #pragma unroll
            for (int j = 0; j < 4; j++) s[i][j] = 0.f;

        const int krow_off = ((lane >> 4) << 3) + (lane & 7);
        const int kdim_off = ((lane >> 3) & 1) * 16;
        #pragma unroll
        for (int ks = 0; ks < 12; ks++) {
            #pragma unroll
            for (int kb4 = 0; kb4 < 4; kb4++) {
                uint32_t r[4];
                ldm_x4(kaddr(kb, kb4 * 16 + krow_off, ks * 32 + kdim_off), r);
                mma_f16(s[2 * kb4],     qa[ks], r[0], r[1]);
                mma_f16(s[2 * kb4 + 1], qa[ks], r[2], r[3]);
            }
        }

        float mx0 = -1e30f, mx1 = -1e30f;
        #pragma unroll
        for (int ni = 0; ni < 8; ni++) {
            mx0 = fmaxf(mx0, fmaxf(s[ni][0], s[ni][1]));
            mx1 = fmaxf(mx1, fmaxf(s[ni][2], s[ni][3]));
        }
        mx0 = fmaxf(mx0, __shfl_xor_sync(0xffffffffu, mx0, 1));
        mx0 = fmaxf(mx0, __shfl_xor_sync(0xffffffffu, mx0, 2));
        mx1 = fmaxf(mx1, __shfl_xor_sync(0xffffffffu, mx1, 1));
        mx1 = fmaxf(mx1, __shfl_xor_sync(0xffffffffu, mx1, 2));

        float mn0 = fmaxf(m0, mx0 * sc);
        float mn1 = fmaxf(m1, mx1 * sc);
        float a0 = __expf(m0 - mn0);
        float a1 = __expf(m1 - mn1);

        float rs0 = 0.f, rs1 = 0.f;
        uint32_t pa[4][4];
        #pragma unroll
        for (int ni = 0; ni < 8; ni++) {
            float p0 = __expf(s[ni][0] * sc - mn0);
            float p1 = __expf(s[ni][1] * sc - mn0);
            float p2 = __expf(s[ni][2] * sc - mn1);
            float p3 = __expf(s[ni][3] * sc - mn1);
            rs0 += p0 + p1;
            rs1 += p2 + p3;
            int kk = ni >> 1;
            if ((ni & 1) == 0) {
                pa[kk][0] = packh2(p0, p1);
                pa[kk][1] = packh2(p2, p3);
            } else {
                pa[kk][2] = packh2(p0, p1);
                pa[kk][3] = packh2(p2, p3);
            }
        }
        rs0 += __shfl_xor_sync(0xffffffffu, rs0, 1);
        rs0 += __shfl_xor_sync(0xffffffffu, rs0, 2);
        rs1 += __shfl_xor_sync(0xffffffffu, rs1, 1);
        rs1 += __shfl_xor_sync(0xffffffffu, rs1, 2);

        l0 = l0 * a0 + rs0;
        l1 = l1 * a1 + rs1;
        m0 = mn0; m1 = mn1;

        #pragma unroll
        for (int nj = 0; nj < 16; nj++) {
            o[nj][0] *= a0; o[nj][1] *= a0;
            o[nj][2] *= a1; o[nj][3] *= a1;
        }

        const int vrow_off = ((lane >> 3) & 1) * 8 + (lane & 7);
        const int vdim_off = (lane >> 4) * 16;
        #pragma unroll
        for (int kk = 0; kk < 4; kk++) {
            #pragma unroll
            for (int nb = 0; nb < 8; nb++) {
                uint32_t r[4];
                ldm_x4_t(vaddr(vb, kk * 16 + vrow_off, nb * 32 + vdim_off), r);
                mma_f16(o[2 * nb],     pa[kk], r[0], r[1]);
                mma_f16(o[2 * nb + 1], pa[kk], r[2], r[3]);
            }
        }
        __syncthreads();
    }

    const float inv0 = 1.f / l0, inv1 = 1.f / l1;
    size_t rbase = (size_t)(b * SEQ + q0 + w * 16 + (lane >> 2)) * HID
                 + h * VH + (lane & 3) * 2;
    #pragma unroll
    for (int nj = 0; nj < 16; nj++) {
        *(uint32_t*)(out + rbase + nj * 8) =
            packh2(o[nj][0] * inv0, o[nj][1] * inv0);
        *(uint32_t*)(out + rbase + 8 * HID + nj * 8) =
            packh2(o[nj][2] * inv1, o[nj][3] * inv1);
    }
}

// =====================================================================
extern "C" void kernel_launch(void* const* d_in, const int* in_sizes, int n_in,
                              void* d_out, int out_size)
{
    const float* x        = (const float*)d_in[0];
    const int*   position = (const int*)  d_in[1];
    const float* Wq_down  = (const float*)d_in[2];
    const float* Wq_up    = (const float*)d_in[3];
    const float* Wkv_down = (const float*)d_in[4];
    const float* Wkv_up   = (const float*)d_in[5];
    const float* Wout     = (const float*)d_in[6];
    float*       out      = (float*)d_out;

    __half *x16, *cqk, *qb, *kvb, *attn, *w;
    cudaGetSymbolAddress((void**)&x16,  g_x16);
    cudaGetSymbolAddress((void**)&cqk,  g_cqk);
    cudaGetSymbolAddress((void**)&qb,   g_q);
    cudaGetSymbolAddress((void**)&kvb,  g_kv);
    cudaGetSymbolAddress((void**)&attn, g_attn);
    cudaGetSymbolAddress((void**)&w,    g_w);

    cudaFuncSetAttribute(gemm_f16, cudaFuncAttributeMaxDynamicSharedMemorySize,
                         GEMM_SMEM);
    cudaFuncSetAttribute(gemm_up, cudaFuncAttributeMaxDynamicSharedMemorySize,
                         GEMM_SMEM);
    cudaFuncSetAttribute(attn_mma, cudaFuncAttributeMaxDynamicSharedMemorySize,
                         ATTN_SMEM);

    // 1. fused conversions (x + all weights), one chip-filling launch
    prep<<<PREP_BLKS, 256>>>(x, Wq_down, Wkv_down, Wq_up, Wkv_up, Wout, x16, w);

    // 2. merged down-projection: cqk = x16 @ [Wq_down|Wkv_down]
    gemm_f16<<<dim3((CQK_W + 127)/128, BS/128), 256, GEMM_SMEM>>>(
        x16, w + O_WDN, cqk, nullptr, BS, CQK_W, HID, HID, CQK_W);

    // 3. fused up-projections: q = cq @ Wq_up  ||  kv = ckv @ Wkv_up
    gemm_up<<<dim3(QW/128 + KVW/128, BS/128), 256, GEMM_SMEM>>>(
        cqk, w + O_WQU, w + O_WKU, qb, kvb);

    // 4. RoPE (q rope dims + k rope in cqk)
    rope_kernel<<<(BS*17*32 + 255)/256, 256>>>(qb, cqk, position);

    // 5. attention
    attn_mma<<<dim3(SEQ/64, HEADS, BATCH), 128, ATTN_SMEM>>>(qb, kvb, cqk, attn);

    // 6. output projection
    gemm_f16<<<dim3(HID/128, BS/128), 256, GEMM_SMEM>>>(
        attn, w + O_WO, nullptr, out, BS, HID, HID, HID, HID);
}